// round 6
// baseline (speedup 1.0000x reference)
#include <cuda_runtime.h>
#include <math.h>

// Problem constants
#define BQ   16
#define SEQ  512
#define NH   16
#define DKH  64
#define DM   1024
#define MROWS (BQ * SEQ)   // 8192

// ---------------------------------------------------------------------------
// Scratch (device globals; allocation-free per harness rules)
// ---------------------------------------------------------------------------
__device__ float g_Q[BQ * NH * SEQ * DKH];            // [b][h][s][d]
__device__ float g_K[BQ * NH * SEQ * DKH];            // [b][h][t][d]
__device__ float g_V[BQ * NH * SEQ * DKH];            // [b][h][t][d]
__device__ float g_P[(size_t)BQ * NH * SEQ * SEQ];    // [b][h][s][t]  scores -> probs
__device__ float g_C[BQ * SEQ * DM];                  // [b][s][h*64+d] context

// ---------------------------------------------------------------------------
// Dense GEMM: C = A @ W^T + bias, M=8192, N=1024, K=1024 (both K-contiguous)
// mode 0/1/2: C = g_Q/g_K/g_V in head layout [b][h][s][d]
// mode 3    : A = g_C, C = C_ext standard row-major (final output proj)
// Tiles: 64x64x16, 256 threads, 4x4 per thread.
// ---------------------------------------------------------------------------
__global__ void __launch_bounds__(256) gemm_proj(const float* __restrict__ A_ext,
                                                 const float* __restrict__ W,
                                                 const float* __restrict__ bias,
                                                 float* __restrict__ C_ext,
                                                 int mode)
{
    __shared__ float As[16][68];   // As[k][m]
    __shared__ float Bs[16][68];   // Bs[k][n]

    const float* A = (mode == 3) ? g_C : A_ext;
    float* C = (mode == 0) ? g_Q : (mode == 1) ? g_K : (mode == 2) ? g_V : C_ext;

    const int tid = threadIdx.x;
    const int m0 = blockIdx.y * 64;
    const int n0 = blockIdx.x * 64;
    const int lr = tid >> 2;            // 0..63 row within tile
    const int lk = (tid & 3) << 2;      // 0,4,8,12 within k-slab
    const int ty = tid >> 4;            // 0..15
    const int tx = tid & 15;            // 0..15

    float acc[4][4] = {};

    const float* Ap = A + (size_t)(m0 + lr) * DM + lk;
    const float* Wp = W + (size_t)(n0 + lr) * DM + lk;

    for (int k0 = 0; k0 < DM; k0 += 16) {
        float4 av = *(const float4*)(Ap + k0);
        float4 bv = *(const float4*)(Wp + k0);
        As[lk + 0][lr] = av.x; As[lk + 1][lr] = av.y;
        As[lk + 2][lr] = av.z; As[lk + 3][lr] = av.w;
        Bs[lk + 0][lr] = bv.x; Bs[lk + 1][lr] = bv.y;
        Bs[lk + 2][lr] = bv.z; Bs[lk + 3][lr] = bv.w;
        __syncthreads();

        #pragma unroll
        for (int k = 0; k < 16; k++) {
            float a[4], b[4];
            *(float4*)a = *(const float4*)&As[k][ty * 4];
            *(float4*)b = *(const float4*)&Bs[k][tx * 4];
            #pragma unroll
            for (int i = 0; i < 4; i++)
                #pragma unroll
                for (int j = 0; j < 4; j++)
                    acc[i][j] += a[i] * b[j];
        }
        __syncthreads();
    }

    #pragma unroll
    for (int i = 0; i < 4; i++) {
        int m = m0 + ty * 4 + i;
        #pragma unroll
        for (int j = 0; j < 4; j++) {
            int n = n0 + tx * 4 + j;
            float v = acc[i][j] + bias[n];
            if (mode < 3) {
                int b = m >> 9, s = m & 511;
                int h = n >> 6, d = n & 63;
                C[((size_t)(b * NH + h) * SEQ + s) * DKH + d] = v;
            } else {
                C[(size_t)m * DM + n] = v;
            }
        }
    }
}

// ---------------------------------------------------------------------------
// Scores: P[b,h,s,t] = (Q.K)/8 + rel_bias[h,s,t]   (64x64 tiles; skip masked)
// ---------------------------------------------------------------------------
__global__ void __launch_bounds__(256) attn_scores(const float* __restrict__ rel_bias)
{
    const int s0 = blockIdx.y * 64;
    const int t0 = blockIdx.x * 64;
    if (t0 > s0 + 63) return;                // fully above diagonal -> never read

    const int bh = blockIdx.z;
    const int h  = bh & 15;
    const float* Qp = g_Q + (size_t)bh * SEQ * DKH;
    const float* Kp = g_K + (size_t)bh * SEQ * DKH;
    float*       Pp = g_P + (size_t)bh * SEQ * SEQ;

    __shared__ float As[16][68];
    __shared__ float Bs[16][68];

    const int tid = threadIdx.x;
    const int lr = tid >> 2;
    const int lk = (tid & 3) << 2;
    const int ty = tid >> 4, tx = tid & 15;

    float acc[4][4] = {};

    for (int k0 = 0; k0 < DKH; k0 += 16) {
        float4 av = *(const float4*)(Qp + (size_t)(s0 + lr) * DKH + k0 + lk);
        float4 bv = *(const float4*)(Kp + (size_t)(t0 + lr) * DKH + k0 + lk);
        As[lk + 0][lr] = av.x; As[lk + 1][lr] = av.y;
        As[lk + 2][lr] = av.z; As[lk + 3][lr] = av.w;
        Bs[lk + 0][lr] = bv.x; Bs[lk + 1][lr] = bv.y;
        Bs[lk + 2][lr] = bv.z; Bs[lk + 3][lr] = bv.w;
        __syncthreads();

        #pragma unroll
        for (int k = 0; k < 16; k++) {
            float a[4], b[4];
            *(float4*)a = *(const float4*)&As[k][ty * 4];
            *(float4*)b = *(const float4*)&Bs[k][tx * 4];
            #pragma unroll
            for (int i = 0; i < 4; i++)
                #pragma unroll
                for (int j = 0; j < 4; j++)
                    acc[i][j] += a[i] * b[j];
        }
        __syncthreads();
    }

    const float inv = 0.125f;   // 1/sqrt(64)
    #pragma unroll
    for (int i = 0; i < 4; i++) {
        int s = s0 + ty * 4 + i;
        #pragma unroll
        for (int j = 0; j < 4; j++) {
            int t = t0 + tx * 4 + j;
            float v = acc[i][j] * inv + rel_bias[((size_t)h * SEQ + s) * SEQ + t];
            Pp[(size_t)s * SEQ + t] = v;   // entries with t>s are never read
        }
    }
}

// ---------------------------------------------------------------------------
// Row softmax with causal mask: reads t in [0, s], writes full 512 row
// (zeros for t > s). One block (128 thr) per row.
// ---------------------------------------------------------------------------
__global__ void __launch_bounds__(128) softmax_rows()
{
    const int row = blockIdx.x;            // (bh * 512 + s)
    const int s   = row & 511;
    const int n   = s + 1;                 // valid length
    float* Pr = g_P + (size_t)row * SEQ;
    const int tid = threadIdx.x;

    float vals[4];
    float mx = -INFINITY;
    #pragma unroll
    for (int i = 0; i < 4; i++) {
        int t = tid + i * 128;
        vals[i] = (t < n) ? Pr[t] : -INFINITY;
        mx = fmaxf(mx, vals[i]);
    }
    #pragma unroll
    for (int o = 16; o; o >>= 1) mx = fmaxf(mx, __shfl_xor_sync(0xffffffffu, mx, o));
    __shared__ float redm[4], reds[4];
    if ((tid & 31) == 0) redm[tid >> 5] = mx;
    __syncthreads();
    mx = fmaxf(fmaxf(redm[0], redm[1]), fmaxf(redm[2], redm[3]));

    float sum = 0.f;
    #pragma unroll
    for (int i = 0; i < 4; i++) {
        int t = tid + i * 128;
        vals[i] = (t < n) ? __expf(vals[i] - mx) : 0.f;
        sum += vals[i];
    }
    #pragma unroll
    for (int o = 16; o; o >>= 1) sum += __shfl_xor_sync(0xffffffffu, sum, o);
    if ((tid & 31) == 0) reds[tid >> 5] = sum;
    __syncthreads();
    sum = reds[0] + reds[1] + reds[2] + reds[3];

    const float w = 1.0f / sum;
    #pragma unroll
    for (int i = 0; i < 4; i++) {
        int t = tid + i * 128;
        Pr[t] = vals[i] * w;
    }
}

// ---------------------------------------------------------------------------
// ctx[b,s,h*64+d] = sum_t P[b,h,s,t] * V[b,h,t,d]   (NN GEMM, k-loop truncated
// at the causal boundary since P is exactly 0 beyond it)
// ---------------------------------------------------------------------------
__global__ void __launch_bounds__(256) attn_ctx()
{
    const int bh = blockIdx.z;
    const int b = bh >> 4, h = bh & 15;
    const int s0 = blockIdx.y * 64;
    const float* Pp = g_P + (size_t)bh * SEQ * SEQ;
    const float* Vp = g_V + (size_t)bh * SEQ * DKH;

    __shared__ float As[16][68];   // P^T: As[k][m]
    __shared__ float Bs[16][68];   // V  : Bs[k][d]

    const int tid = threadIdx.x;
    const int lr = tid >> 2;
    const int lk = (tid & 3) << 2;
    const int vr = tid >> 4;            // 0..15 (t within slab)
    const int vc = (tid & 15) << 2;     // 0..60 (d, float4)
    const int ty = tid >> 4, tx = tid & 15;

    float acc[4][4] = {};
    const int kmax = s0 + 64;           // probs zero for t > s0+63

    for (int k0 = 0; k0 < kmax; k0 += 16) {
        float4 av = *(const float4*)(Pp + (size_t)(s0 + lr) * SEQ + k0 + lk);
        float4 bv = *(const float4*)(Vp + (size_t)(k0 + vr) * DKH + vc);
        As[lk + 0][lr] = av.x; As[lk + 1][lr] = av.y;
        As[lk + 2][lr] = av.z; As[lk + 3][lr] = av.w;
        *(float4*)&Bs[vr][vc] = bv;
        __syncthreads();

        #pragma unroll
        for (int k = 0; k < 16; k++) {
            float a[4], bvv[4];
            *(float4*)a   = *(const float4*)&As[k][ty * 4];
            *(float4*)bvv = *(const float4*)&Bs[k][tx * 4];
            #pragma unroll
            for (int i = 0; i < 4; i++)
                #pragma unroll
                for (int j = 0; j < 4; j++)
                    acc[i][j] += a[i] * bvv[j];
        }
        __syncthreads();
    }

    #pragma unroll
    for (int i = 0; i < 4; i++) {
        int s = s0 + ty * 4 + i;
        #pragma unroll
        for (int j = 0; j < 4; j++) {
            int d = tx * 4 + j;
            g_C[((size_t)b * SEQ + s) * DM + h * DKH + d] = acc[i][j];
        }
    }
}

// ---------------------------------------------------------------------------
// attn_mean[b,s,t] = (1/16) * sum_h P[b,h,s,t]
// ---------------------------------------------------------------------------
__global__ void __launch_bounds__(256) attn_mean_kernel(float* __restrict__ outp)
{
    size_t idx = (size_t)blockIdx.x * 256 + threadIdx.x;   // < B*S*S
    int t = (int)(idx & 511);
    int s = (int)((idx >> 9) & 511);
    int b = (int)(idx >> 18);
    const float* base = g_P + ((size_t)(b * NH) * SEQ + s) * SEQ + t;
    float sum = 0.f;
    #pragma unroll
    for (int h = 0; h < NH; h++) sum += base[(size_t)h * SEQ * SEQ];
    outp[idx] = sum * (1.0f / 16.0f);
}

// ---------------------------------------------------------------------------
// Launch
// ---------------------------------------------------------------------------
extern "C" void kernel_launch(void* const* d_in, const int* in_sizes, int n_in,
                              void* d_out, int out_size)
{
    const float* query    = (const float*)d_in[0];
    const float* key      = (const float*)d_in[1];
    const float* value    = (const float*)d_in[2];
    const float* wq_w     = (const float*)d_in[3];
    const float* wq_b     = (const float*)d_in[4];
    const float* wk_w     = (const float*)d_in[5];
    const float* wk_b     = (const float*)d_in[6];
    const float* wv_w     = (const float*)d_in[7];
    const float* wv_b     = (const float*)d_in[8];
    const float* wo_w     = (const float*)d_in[9];
    const float* wo_b     = (const float*)d_in[10];
    const float* rel_bias = (const float*)d_in[11];

    float* out       = (float*)d_out;
    float* attn_mean = out + (size_t)BQ * SEQ * DM;

    dim3 gP(DM / 64, MROWS / 64);            // 16 x 128

    gemm_proj<<<gP, 256>>>(query, wq_w, wq_b, nullptr, 0);   // -> g_Q
    gemm_proj<<<gP, 256>>>(key,   wk_w, wk_b, nullptr, 1);   // -> g_K
    gemm_proj<<<gP, 256>>>(value, wv_w, wv_b, nullptr, 2);   // -> g_V

    attn_scores<<<dim3(8, 8, BQ * NH), 256>>>(rel_bias);
    softmax_rows<<<BQ * NH * SEQ, 128>>>();
    attn_ctx<<<dim3(1, 8, BQ * NH), 256>>>();
    attn_mean_kernel<<<(BQ * SEQ * SEQ) / 256, 256>>>(attn_mean);

    gemm_proj<<<gP, 256>>>(nullptr, wo_w, wo_b, out, 3);     // g_C -> out
}

// round 9
// speedup vs baseline: 2.4949x; 2.4949x over previous
#include <cuda_runtime.h>
#include <math.h>
#include <stdint.h>

// Problem constants
#define BQ   16
#define SEQ  512
#define NH   16
#define DKH  64
#define DM   1024
#define MROWS (BQ * SEQ)   // 8192

// ---------------------------------------------------------------------------
// Scratch (device globals; allocation-free per harness rules)
// ---------------------------------------------------------------------------
__device__ float g_Q[BQ * NH * SEQ * DKH];            // [b][h][s][d]
__device__ float g_K[BQ * NH * SEQ * DKH];            // [b][h][t][d]
__device__ float g_V[BQ * NH * SEQ * DKH];            // [b][h][t][d]
__device__ float g_P[(size_t)BQ * NH * SEQ * SEQ];    // [b][h][s][t]
__device__ float g_C[BQ * SEQ * DM];                  // [b][s][h*64+d]

// ---------------------------------------------------------------------------
// PTX helpers (base-target legal: sm_80+ features only)
// ---------------------------------------------------------------------------
__device__ __forceinline__ uint32_t smem_u32(const void* p) {
    return (uint32_t)__cvta_generic_to_shared((void*)p);
}
__device__ __forceinline__ void cp_async16(uint32_t dst, const void* src) {
    asm volatile("cp.async.cg.shared.global [%0], [%1], 16;" :: "r"(dst), "l"(src));
}
__device__ __forceinline__ void cp_commit() {
    asm volatile("cp.async.commit_group;" ::: "memory");
}
template <int N> __device__ __forceinline__ void cp_wait() {
    asm volatile("cp.async.wait_group %0;" :: "n"(N) : "memory");
}
__device__ __forceinline__ void ldsm_x4(uint32_t& r0, uint32_t& r1, uint32_t& r2,
                                        uint32_t& r3, uint32_t addr) {
    asm volatile("ldmatrix.sync.aligned.m8n8.x4.shared.b16 {%0,%1,%2,%3}, [%4];"
                 : "=r"(r0), "=r"(r1), "=r"(r2), "=r"(r3) : "r"(addr));
}
__device__ __forceinline__ uint32_t f2tf32(uint32_t x) {
    uint32_t y;
    asm("cvt.rna.tf32.f32 %0, %1;" : "=r"(y) : "f"(__uint_as_float(x)));
    return y;
}
__device__ __forceinline__ void mma_tf32(float* c, const uint32_t* a, const uint32_t* b) {
    asm volatile(
        "mma.sync.aligned.m16n8k8.row.col.f32.tf32.tf32.f32 "
        "{%0,%1,%2,%3}, {%4,%5,%6,%7}, {%8,%9}, {%0,%1,%2,%3};"
        : "+f"(c[0]), "+f"(c[1]), "+f"(c[2]), "+f"(c[3])
        : "r"(a[0]), "r"(a[1]), "r"(a[2]), "r"(a[3]), "r"(b[0]), "r"(b[1]));
}

// ---------------------------------------------------------------------------
// tf32 mma.sync GEMM: C = A @ W^T + bias; M=8192, N=1024, K=1024
// Tile 128x128, K-chunk 32, 3-stage cp.async pipeline.
// SMEM row stride 36 floats (144B) -> conflict-free ldmatrix, no swizzle.
// mode 0/1/2: head-layout output to g_Q/g_K/g_V ; mode 3: g_C -> C_ext
// ---------------------------------------------------------------------------
#define KC     32
#define NSTG   3
#define ROWB   144                      // bytes per smem row (36 floats)
#define ASTG   (128 * ROWB)             // 18432 B per matrix per stage
#define STGB   (2 * ASTG)               // 36864 B per stage
#define SMEM_DYN (NSTG * STGB)          // 110592 B

__global__ void __launch_bounds__(256, 1)
gemm_tc(const float* __restrict__ A_ext, const float* __restrict__ W,
        const float* __restrict__ bias, float* __restrict__ C_ext, int mode)
{
    extern __shared__ char smem_raw[];
    __shared__ float bias_s[128];
    const uint32_t sb = smem_u32(smem_raw);

    const float* A = (mode == 3) ? g_C : A_ext;
    const int tid  = threadIdx.x;
    const int wid  = tid >> 5, lane = tid & 31;
    const int wm   = wid >> 2, wn = wid & 3;          // warp grid 2 x 4
    const int m0   = blockIdx.y * 128, n0 = blockIdx.x * 128;

    if (tid < 128) bias_s[tid] = bias[n0 + tid];

    float acc[4][4][4] = {};                          // [mi][ni][reg]

    auto load_chunk = [&](int c) {
        uint32_t base = sb + (uint32_t)(c % NSTG) * STGB;
        const float* Ag = A + (size_t)m0 * DM + c * KC;
        const float* Wg = W + (size_t)n0 * DM + c * KC;
        #pragma unroll
        for (int i = 0; i < 4; i++) {
            int q = tid + 256 * i;                    // 0..1023
            int r = q >> 3, c16 = q & 7;              // row, 16B segment
            uint32_t dst = base + (uint32_t)(r * ROWB + c16 * 16);
            cp_async16(dst,        (const char*)(Ag + (size_t)r * DM) + c16 * 16);
            cp_async16(dst + ASTG, (const char*)(Wg + (size_t)r * DM) + c16 * 16);
        }
    };

    load_chunk(0); cp_commit();
    load_chunk(1); cp_commit();

    // Fragment ldmatrix lane addressing (within a stage):
    // A x4: mats = {m0-7 k0-3, m8-15 k0-3, m0-7 k4-7, m8-15 k4-7}
    const int a_row  = lane & 15;
    const int a_half = (lane >> 4) & 1;
    const uint32_t a_off0 = (uint32_t)((wm * 64 + a_row) * ROWB + a_half * 16);
    // B x4: mats = {n0-7 k0-3, n0-7 k4-7, n8-15 k0-3, n8-15 k4-7}
    const int bg     = lane >> 3;
    const int b_nrow = (bg >> 1) * 8 + (lane & 7);
    const int b_half = bg & 1;
    const uint32_t b_off0 = (uint32_t)(ASTG + (wn * 32 + b_nrow) * ROWB + b_half * 16);

    const int NCH = DM / KC;                          // 32
    for (int c = 0; c < NCH; c++) {
        cp_wait<1>();
        __syncthreads();
        uint32_t base = sb + (uint32_t)(c % NSTG) * STGB;

        #pragma unroll
        for (int kk = 0; kk < 4; kk++) {
            uint32_t a[4][4], b[4][2];
            #pragma unroll
            for (int mi = 0; mi < 4; mi++)
                ldsm_x4(a[mi][0], a[mi][1], a[mi][2], a[mi][3],
                        base + a_off0 + (uint32_t)(mi * 16 * ROWB + kk * 32));
            #pragma unroll
            for (int np = 0; np < 2; np++) {
                uint32_t r0, r1, r2, r3;
                ldsm_x4(r0, r1, r2, r3,
                        base + b_off0 + (uint32_t)(np * 16 * ROWB + kk * 32));
                b[np * 2][0] = r0;     b[np * 2][1] = r1;
                b[np * 2 + 1][0] = r2; b[np * 2 + 1][1] = r3;
            }
            #pragma unroll
            for (int mi = 0; mi < 4; mi++)
                #pragma unroll
                for (int j = 0; j < 4; j++) a[mi][j] = f2tf32(a[mi][j]);
            #pragma unroll
            for (int ni = 0; ni < 4; ni++) {
                b[ni][0] = f2tf32(b[ni][0]);
                b[ni][1] = f2tf32(b[ni][1]);
            }
            #pragma unroll
            for (int mi = 0; mi < 4; mi++)
                #pragma unroll
                for (int ni = 0; ni < 4; ni++)
                    mma_tf32(acc[mi][ni], a[mi], b[ni]);
        }

        int cn = c + 2;
        if (cn < NCH) load_chunk(cn);
        cp_commit();                                  // one group per iteration
    }

    // ---------------- epilogue: regs -> smem -> coalesced gmem -------------
    __syncthreads();                                  // smem stages now free
    float* smemT = (float*)smem_raw;                  // 128 x 132 floats
    {
        const int r0 = wm * 64 + (lane >> 2);
        const int cc0 = wn * 32 + 2 * (lane & 3);
        #pragma unroll
        for (int mi = 0; mi < 4; mi++) {
            #pragma unroll
            for (int ni = 0; ni < 4; ni++) {
                int r = r0 + mi * 16, cc = cc0 + ni * 8;
                smemT[r * 132 + cc]           = acc[mi][ni][0];
                smemT[r * 132 + cc + 1]       = acc[mi][ni][1];
                smemT[(r + 8) * 132 + cc]     = acc[mi][ni][2];
                smemT[(r + 8) * 132 + cc + 1] = acc[mi][ni][3];
            }
        }
    }
    __syncthreads();

    if (mode < 3) {
        float* Cq = (mode == 0) ? g_Q : (mode == 1) ? g_K : g_V;
        const int bq = m0 >> 9, s_base = m0 & 511;
        #pragma unroll
        for (int i = 0; i < 16; i++) {
            int q = tid + 256 * i;                    // 0..4095 float4 chunks
            int r = q >> 5, c4 = (q & 31) * 4;
            float4 v;
            v.x = smemT[r * 132 + c4 + 0] + bias_s[c4 + 0];
            v.y = smemT[r * 132 + c4 + 1] + bias_s[c4 + 1];
            v.z = smemT[r * 132 + c4 + 2] + bias_s[c4 + 2];
            v.w = smemT[r * 132 + c4 + 3] + bias_s[c4 + 3];
            int n = n0 + c4;
            int h = n >> 6, db = n & 63;
            *(float4*)(Cq + ((size_t)(bq * NH + h) * SEQ + s_base + r) * DKH + db) = v;
        }
    } else {
        #pragma unroll
        for (int i = 0; i < 16; i++) {
            int q = tid + 256 * i;
            int r = q >> 5, c4 = (q & 31) * 4;
            float4 v;
            v.x = smemT[r * 132 + c4 + 0] + bias_s[c4 + 0];
            v.y = smemT[r * 132 + c4 + 1] + bias_s[c4 + 1];
            v.z = smemT[r * 132 + c4 + 2] + bias_s[c4 + 2];
            v.w = smemT[r * 132 + c4 + 3] + bias_s[c4 + 3];
            *(float4*)(C_ext + (size_t)(m0 + r) * DM + n0 + c4) = v;
        }
    }
}

// ---------------------------------------------------------------------------
// Scores: P[b,h,s,t] = (Q.K)/8 + rel_bias[h,s,t]   (64x64 tiles; skip masked)
// ---------------------------------------------------------------------------
__global__ void __launch_bounds__(256) attn_scores(const float* __restrict__ rel_bias)
{
    const int s0 = blockIdx.y * 64;
    const int t0 = blockIdx.x * 64;
    if (t0 > s0 + 63) return;

    const int bh = blockIdx.z;
    const int h  = bh & 15;
    const float* Qp = g_Q + (size_t)bh * SEQ * DKH;
    const float* Kp = g_K + (size_t)bh * SEQ * DKH;
    float*       Pp = g_P + (size_t)bh * SEQ * SEQ;

    __shared__ float As[16][68];
    __shared__ float Bs[16][68];

    const int tid = threadIdx.x;
    const int lr = tid >> 2;
    const int lk = (tid & 3) << 2;
    const int ty = tid >> 4, tx = tid & 15;

    float acc[4][4] = {};

    for (int k0 = 0; k0 < DKH; k0 += 16) {
        float4 av = *(const float4*)(Qp + (size_t)(s0 + lr) * DKH + k0 + lk);
        float4 bv = *(const float4*)(Kp + (size_t)(t0 + lr) * DKH + k0 + lk);
        As[lk + 0][lr] = av.x; As[lk + 1][lr] = av.y;
        As[lk + 2][lr] = av.z; As[lk + 3][lr] = av.w;
        Bs[lk + 0][lr] = bv.x; Bs[lk + 1][lr] = bv.y;
        Bs[lk + 2][lr] = bv.z; Bs[lk + 3][lr] = bv.w;
        __syncthreads();

        #pragma unroll
        for (int k = 0; k < 16; k++) {
            float a[4], b[4];
            *(float4*)a = *(const float4*)&As[k][ty * 4];
            *(float4*)b = *(const float4*)&Bs[k][tx * 4];
            #pragma unroll
            for (int i = 0; i < 4; i++)
                #pragma unroll
                for (int j = 0; j < 4; j++)
                    acc[i][j] += a[i] * b[j];
        }
        __syncthreads();
    }

    const float inv = 0.125f;
    #pragma unroll
    for (int i = 0; i < 4; i++) {
        int s = s0 + ty * 4 + i;
        #pragma unroll
        for (int j = 0; j < 4; j++) {
            int t = t0 + tx * 4 + j;
            float v = acc[i][j] * inv + rel_bias[((size_t)h * SEQ + s) * SEQ + t];
            Pp[(size_t)s * SEQ + t] = v;
        }
    }
}

// ---------------------------------------------------------------------------
// Row softmax with causal mask
// ---------------------------------------------------------------------------
__global__ void __launch_bounds__(128) softmax_rows()
{
    const int row = blockIdx.x;
    const int s   = row & 511;
    const int n   = s + 1;
    float* Pr = g_P + (size_t)row * SEQ;
    const int tid = threadIdx.x;

    float vals[4];
    float mx = -INFINITY;
    #pragma unroll
    for (int i = 0; i < 4; i++) {
        int t = tid + i * 128;
        vals[i] = (t < n) ? Pr[t] : -INFINITY;
        mx = fmaxf(mx, vals[i]);
    }
    #pragma unroll
    for (int o = 16; o; o >>= 1) mx = fmaxf(mx, __shfl_xor_sync(0xffffffffu, mx, o));
    __shared__ float redm[4], reds[4];
    if ((tid & 31) == 0) redm[tid >> 5] = mx;
    __syncthreads();
    mx = fmaxf(fmaxf(redm[0], redm[1]), fmaxf(redm[2], redm[3]));

    float sum = 0.f;
    #pragma unroll
    for (int i = 0; i < 4; i++) {
        int t = tid + i * 128;
        vals[i] = (t < n) ? __expf(vals[i] - mx) : 0.f;
        sum += vals[i];
    }
    #pragma unroll
    for (int o = 16; o; o >>= 1) sum += __shfl_xor_sync(0xffffffffu, sum, o);
    if ((tid & 31) == 0) reds[tid >> 5] = sum;
    __syncthreads();
    sum = reds[0] + reds[1] + reds[2] + reds[3];

    const float w = 1.0f / sum;
    #pragma unroll
    for (int i = 0; i < 4; i++) {
        int t = tid + i * 128;
        Pr[t] = vals[i] * w;
    }
}

// ---------------------------------------------------------------------------
// ctx[b,s,h*64+d] = sum_t P[b,h,s,t] * V[b,h,t,d]
// ---------------------------------------------------------------------------
__global__ void __launch_bounds__(256) attn_ctx()
{
    const int bh = blockIdx.z;
    const int b = bh >> 4, h = bh & 15;
    const int s0 = blockIdx.y * 64;
    const float* Pp = g_P + (size_t)bh * SEQ * SEQ;
    const float* Vp = g_V + (size_t)bh * SEQ * DKH;

    __shared__ float As[16][68];
    __shared__ float Bs[16][68];

    const int tid = threadIdx.x;
    const int lr = tid >> 2;
    const int lk = (tid & 3) << 2;
    const int vr = tid >> 4;
    const int vc = (tid & 15) << 2;
    const int ty = tid >> 4, tx = tid & 15;

    float acc[4][4] = {};
    const int kmax = s0 + 64;

    for (int k0 = 0; k0 < kmax; k0 += 16) {
        float4 av = *(const float4*)(Pp + (size_t)(s0 + lr) * SEQ + k0 + lk);
        float4 bv = *(const float4*)(Vp + (size_t)(k0 + vr) * DKH + vc);
        As[lk + 0][lr] = av.x; As[lk + 1][lr] = av.y;
        As[lk + 2][lr] = av.z; As[lk + 3][lr] = av.w;
        *(float4*)&Bs[vr][vc] = bv;
        __syncthreads();

        #pragma unroll
        for (int k = 0; k < 16; k++) {
            float a[4], bvv[4];
            *(float4*)a   = *(const float4*)&As[k][ty * 4];
            *(float4*)bvv = *(const float4*)&Bs[k][tx * 4];
            #pragma unroll
            for (int i = 0; i < 4; i++)
                #pragma unroll
                for (int j = 0; j < 4; j++)
                    acc[i][j] += a[i] * bvv[j];
        }
        __syncthreads();
    }

    #pragma unroll
    for (int i = 0; i < 4; i++) {
        int s = s0 + ty * 4 + i;
        #pragma unroll
        for (int j = 0; j < 4; j++) {
            int d = tx * 4 + j;
            g_C[((size_t)b * SEQ + s) * DM + h * DKH + d] = acc[i][j];
        }
    }
}

// ---------------------------------------------------------------------------
// attn_mean[b,s,t] = (1/16) * sum_h P[b,h,s,t]
// ---------------------------------------------------------------------------
__global__ void __launch_bounds__(256) attn_mean_kernel(float* __restrict__ outp)
{
    size_t idx = (size_t)blockIdx.x * 256 + threadIdx.x;
    int t = (int)(idx & 511);
    int s = (int)((idx >> 9) & 511);
    int b = (int)(idx >> 18);
    const float* base = g_P + ((size_t)(b * NH) * SEQ + s) * SEQ + t;
    float sum = 0.f;
    #pragma unroll
    for (int h = 0; h < NH; h++) sum += base[(size_t)h * SEQ * SEQ];
    outp[idx] = sum * (1.0f / 16.0f);
}

// ---------------------------------------------------------------------------
// Launch
// ---------------------------------------------------------------------------
extern "C" void kernel_launch(void* const* d_in, const int* in_sizes, int n_in,
                              void* d_out, int out_size)
{
    const float* query    = (const float*)d_in[0];
    const float* key      = (const float*)d_in[1];
    const float* value    = (const float*)d_in[2];
    const float* wq_w     = (const float*)d_in[3];
    const float* wq_b     = (const float*)d_in[4];
    const float* wk_w     = (const float*)d_in[5];
    const float* wk_b     = (const float*)d_in[6];
    const float* wv_w     = (const float*)d_in[7];
    const float* wv_b     = (const float*)d_in[8];
    const float* wo_w     = (const float*)d_in[9];
    const float* wo_b     = (const float*)d_in[10];
    const float* rel_bias = (const float*)d_in[11];

    float* out       = (float*)d_out;
    float* attn_mean = out + (size_t)BQ * SEQ * DM;

    static int smem_set = 0;
    if (!smem_set) {
        cudaFuncSetAttribute(gemm_tc, cudaFuncAttributeMaxDynamicSharedMemorySize, SMEM_DYN);
        smem_set = 1;
    }

    dim3 gG(DM / 128, MROWS / 128);          // (8, 64)

    gemm_tc<<<gG, 256, SMEM_DYN>>>(query, wq_w, wq_b, nullptr, 0);   // -> g_Q
    gemm_tc<<<gG, 256, SMEM_DYN>>>(key,   wk_w, wk_b, nullptr, 1);   // -> g_K
    gemm_tc<<<gG, 256, SMEM_DYN>>>(value, wv_w, wv_b, nullptr, 2);   // -> g_V

    attn_scores<<<dim3(8, 8, BQ * NH), 256>>>(rel_bias);
    softmax_rows<<<BQ * NH * SEQ, 128>>>();
    attn_ctx<<<dim3(1, 8, BQ * NH), 256>>>();
    attn_mean_kernel<<<(BQ * SEQ * SEQ) / 256, 256>>>(attn_mean);

    gemm_tc<<<gG, 256, SMEM_DYN>>>(nullptr, wo_w, wo_b, out, 3);     // g_C -> out
}

// round 10
// speedup vs baseline: 2.9609x; 1.1868x over previous
#include <cuda_runtime.h>
#include <math.h>
#include <stdint.h>

// Problem constants
#define BQ   16
#define SEQ  512
#define NH   16
#define DKH  64
#define DM   1024
#define MROWS (BQ * SEQ)   // 8192

// ---------------------------------------------------------------------------
// Scratch (device globals; allocation-free per harness rules)
// ---------------------------------------------------------------------------
__device__ float g_Q[BQ * NH * SEQ * DKH];            // [b][h][s][d]
__device__ float g_K[BQ * NH * SEQ * DKH];            // [b][h][t][d]
__device__ float g_Vt[BQ * NH * DKH * SEQ];           // [b][h][d][t]  (transposed V)
__device__ float g_P[(size_t)BQ * NH * SEQ * SEQ];    // [b][h][s][t]  probs (lower tri)
__device__ float g_C[BQ * SEQ * DM];                  // [b][s][h*64+d]

// ---------------------------------------------------------------------------
// PTX helpers (base-target legal: sm_80+ features only)
// ---------------------------------------------------------------------------
__device__ __forceinline__ uint32_t smem_u32(const void* p) {
    return (uint32_t)__cvta_generic_to_shared((void*)p);
}
__device__ __forceinline__ void cp_async16(uint32_t dst, const void* src) {
    asm volatile("cp.async.cg.shared.global [%0], [%1], 16;" :: "r"(dst), "l"(src));
}
__device__ __forceinline__ void cp_commit() {
    asm volatile("cp.async.commit_group;" ::: "memory");
}
template <int N> __device__ __forceinline__ void cp_wait() {
    asm volatile("cp.async.wait_group %0;" :: "n"(N) : "memory");
}
__device__ __forceinline__ void ldsm_x4(uint32_t& r0, uint32_t& r1, uint32_t& r2,
                                        uint32_t& r3, uint32_t addr) {
    asm volatile("ldmatrix.sync.aligned.m8n8.x4.shared.b16 {%0,%1,%2,%3}, [%4];"
                 : "=r"(r0), "=r"(r1), "=r"(r2), "=r"(r3) : "r"(addr));
}
__device__ __forceinline__ uint32_t f2tf32(uint32_t x) {
    uint32_t y;
    asm("cvt.rna.tf32.f32 %0, %1;" : "=r"(y) : "f"(__uint_as_float(x)));
    return y;
}
__device__ __forceinline__ void mma_tf32(float* c, const uint32_t* a, const uint32_t* b) {
    asm volatile(
        "mma.sync.aligned.m16n8k8.row.col.f32.tf32.tf32.f32 "
        "{%0,%1,%2,%3}, {%4,%5,%6,%7}, {%8,%9}, {%0,%1,%2,%3};"
        : "+f"(c[0]), "+f"(c[1]), "+f"(c[2]), "+f"(c[3])
        : "r"(a[0]), "r"(a[1]), "r"(a[2]), "r"(a[3]), "r"(b[0]), "r"(b[1]));
}

// ---------------------------------------------------------------------------
// tf32 mma.sync GEMM: C = A @ W^T + bias; M=8192, N=1024, K=1024
// Tile 128x128, K-chunk 32, 3-stage cp.async pipeline.
// mode 0/1: head-layout to g_Q/g_K ; mode 2: TRANSPOSED to g_Vt ; mode 3: g_C -> C_ext
// ---------------------------------------------------------------------------
#define KC     32
#define NSTG   3
#define ROWB   144                      // bytes per smem row (36 floats)
#define ASTG   (128 * ROWB)             // 18432 B per matrix per stage
#define STGB   (2 * ASTG)               // 36864 B per stage
#define SMEM_DYN (NSTG * STGB)          // 110592 B
#define EPS    133                      // epilogue smem row stride (floats)

__global__ void __launch_bounds__(256, 1)
gemm_tc(const float* __restrict__ A_ext, const float* __restrict__ W,
        const float* __restrict__ bias, float* __restrict__ C_ext, int mode)
{
    extern __shared__ char smem_raw[];
    __shared__ float bias_s[128];
    const uint32_t sb = smem_u32(smem_raw);

    const float* A = (mode == 3) ? g_C : A_ext;
    const int tid  = threadIdx.x;
    const int wid  = tid >> 5, lane = tid & 31;
    const int wm   = wid >> 2, wn = wid & 3;          // warp grid 2 x 4
    const int m0   = blockIdx.y * 128, n0 = blockIdx.x * 128;

    if (tid < 128) bias_s[tid] = bias[n0 + tid];

    float acc[4][4][4] = {};                          // [mi][ni][reg]

    auto load_chunk = [&](int c) {
        uint32_t base = sb + (uint32_t)(c % NSTG) * STGB;
        const float* Ag = A + (size_t)m0 * DM + c * KC;
        const float* Wg = W + (size_t)n0 * DM + c * KC;
        #pragma unroll
        for (int i = 0; i < 4; i++) {
            int q = tid + 256 * i;                    // 0..1023
            int r = q >> 3, c16 = q & 7;              // row, 16B segment
            uint32_t dst = base + (uint32_t)(r * ROWB + c16 * 16);
            cp_async16(dst,        (const char*)(Ag + (size_t)r * DM) + c16 * 16);
            cp_async16(dst + ASTG, (const char*)(Wg + (size_t)r * DM) + c16 * 16);
        }
    };

    load_chunk(0); cp_commit();
    load_chunk(1); cp_commit();

    const int a_row  = lane & 15;
    const int a_half = (lane >> 4) & 1;
    const uint32_t a_off0 = (uint32_t)((wm * 64 + a_row) * ROWB + a_half * 16);
    const int bg     = lane >> 3;
    const int b_nrow = (bg >> 1) * 8 + (lane & 7);
    const int b_half = bg & 1;
    const uint32_t b_off0 = (uint32_t)(ASTG + (wn * 32 + b_nrow) * ROWB + b_half * 16);

    const int NCH = DM / KC;                          // 32
    for (int c = 0; c < NCH; c++) {
        cp_wait<1>();
        __syncthreads();
        uint32_t base = sb + (uint32_t)(c % NSTG) * STGB;

        #pragma unroll
        for (int kk = 0; kk < 4; kk++) {
            uint32_t a[4][4], b[4][2];
            #pragma unroll
            for (int mi = 0; mi < 4; mi++)
                ldsm_x4(a[mi][0], a[mi][1], a[mi][2], a[mi][3],
                        base + a_off0 + (uint32_t)(mi * 16 * ROWB + kk * 32));
            #pragma unroll
            for (int np = 0; np < 2; np++) {
                uint32_t r0, r1, r2, r3;
                ldsm_x4(r0, r1, r2, r3,
                        base + b_off0 + (uint32_t)(np * 16 * ROWB + kk * 32));
                b[np * 2][0] = r0;     b[np * 2][1] = r1;
                b[np * 2 + 1][0] = r2; b[np * 2 + 1][1] = r3;
            }
            #pragma unroll
            for (int mi = 0; mi < 4; mi++)
                #pragma unroll
                for (int j = 0; j < 4; j++) a[mi][j] = f2tf32(a[mi][j]);
            #pragma unroll
            for (int ni = 0; ni < 4; ni++) {
                b[ni][0] = f2tf32(b[ni][0]);
                b[ni][1] = f2tf32(b[ni][1]);
            }
            #pragma unroll
            for (int mi = 0; mi < 4; mi++)
                #pragma unroll
                for (int ni = 0; ni < 4; ni++)
                    mma_tf32(acc[mi][ni], a[mi], b[ni]);
        }

        int cn = c + 2;
        if (cn < NCH) load_chunk(cn);
        cp_commit();                                  // one group per iteration
    }

    // ---------------- epilogue: regs -> smem -> coalesced gmem -------------
    __syncthreads();
    float* smemT = (float*)smem_raw;                  // 128 x EPS floats
    {
        const int r0 = wm * 64 + (lane >> 2);
        const int cc0 = wn * 32 + 2 * (lane & 3);
        #pragma unroll
        for (int mi = 0; mi < 4; mi++) {
            #pragma unroll
            for (int ni = 0; ni < 4; ni++) {
                int r = r0 + mi * 16, cc = cc0 + ni * 8;
                smemT[r * EPS + cc]           = acc[mi][ni][0];
                smemT[r * EPS + cc + 1]       = acc[mi][ni][1];
                smemT[(r + 8) * EPS + cc]     = acc[mi][ni][2];
                smemT[(r + 8) * EPS + cc + 1] = acc[mi][ni][3];
            }
        }
    }
    __syncthreads();

    const int bq = m0 >> 9, s_base = m0 & 511;
    if (mode == 2) {
        // transposed store: g_Vt[b][h][d][t]
        #pragma unroll
        for (int i = 0; i < 16; i++) {
            int q = tid + 256 * i;                    // 0..4095
            int cc = q >> 5;                          // n-col 0..127
            int sc4 = (q & 31) * 4;                   // s-chunk
            float4 v;
            v.x = smemT[(sc4 + 0) * EPS + cc] + bias_s[cc];
            v.y = smemT[(sc4 + 1) * EPS + cc] + bias_s[cc];
            v.z = smemT[(sc4 + 2) * EPS + cc] + bias_s[cc];
            v.w = smemT[(sc4 + 3) * EPS + cc] + bias_s[cc];
            int n = n0 + cc;
            int h = n >> 6, d = n & 63;
            *(float4*)(g_Vt + ((size_t)(bq * NH + h) * DKH + d) * SEQ + s_base + sc4) = v;
        }
    } else if (mode < 2) {
        float* Cq = (mode == 0) ? g_Q : g_K;
        #pragma unroll
        for (int i = 0; i < 16; i++) {
            int q = tid + 256 * i;
            int r = q >> 5, c4 = (q & 31) * 4;
            float4 v;
            v.x = smemT[r * EPS + c4 + 0] + bias_s[c4 + 0];
            v.y = smemT[r * EPS + c4 + 1] + bias_s[c4 + 1];
            v.z = smemT[r * EPS + c4 + 2] + bias_s[c4 + 2];
            v.w = smemT[r * EPS + c4 + 3] + bias_s[c4 + 3];
            int n = n0 + c4;
            int h = n >> 6, db = n & 63;
            *(float4*)(Cq + ((size_t)(bq * NH + h) * SEQ + s_base + r) * DKH + db) = v;
        }
    } else {
        #pragma unroll
        for (int i = 0; i < 16; i++) {
            int q = tid + 256 * i;
            int r = q >> 5, c4 = (q & 31) * 4;
            float4 v;
            v.x = smemT[r * EPS + c4 + 0] + bias_s[c4 + 0];
            v.y = smemT[r * EPS + c4 + 1] + bias_s[c4 + 1];
            v.z = smemT[r * EPS + c4 + 2] + bias_s[c4 + 2];
            v.w = smemT[r * EPS + c4 + 3] + bias_s[c4 + 3];
            *(float4*)(C_ext + (size_t)(m0 + r) * DM + n0 + c4) = v;
        }
    }
}

// ---------------------------------------------------------------------------
// FUSED scores + bias + causal softmax (tf32 mma):
//   block = (bh, s-tile of 64 rows); computes full score strip in smem,
//   softmaxes in place, writes probs (lower-triangle region) to g_P once.
// ---------------------------------------------------------------------------
#define FS_SCS   516                          // score row stride (floats)
#define FS_Q_OFF (64 * FS_SCS * 4)            // 132096
#define FS_K_OFF (FS_Q_OFF + 64 * 272)        // 149504
#define FS_SMEM  (FS_K_OFF + 2 * 64 * 272)    // 184320

__global__ void __launch_bounds__(256, 1)
attn_fused(const float* __restrict__ rel_bias)
{
    extern __shared__ char sm[];
    float* sc = (float*)sm;
    const uint32_t sb = smem_u32(sm);
    const uint32_t qb = sb + FS_Q_OFF;

    const int bh = blockIdx.x, st = blockIdx.y;
    const int h  = bh & 15;
    const int s0 = st * 64;
    const int nt = st + 1;

    const float* Qp = g_Q + (size_t)bh * SEQ * DKH;
    const float* Kp = g_K + (size_t)bh * SEQ * DKH;
    const float* rb = rel_bias + (size_t)h * SEQ * SEQ;
    float* Pp = g_P + (size_t)bh * SEQ * SEQ;

    const int tid = threadIdx.x, wid = tid >> 5, lane = tid & 31;
    const int wm = wid >> 2, wn = wid & 3;            // 2 x 4 warps, tile 64x64

    // group 0: Q tile + K tile 0
    #pragma unroll
    for (int i = 0; i < 4; i++) {
        int q = tid + 256 * i;
        int r = q >> 4, seg = q & 15;
        cp_async16(qb + (uint32_t)(r * 272 + seg * 16), Qp + (size_t)(s0 + r) * DKH + seg * 4);
        cp_async16(sb + FS_K_OFF + (uint32_t)(r * 272 + seg * 16), Kp + (size_t)r * DKH + seg * 4);
    }
    cp_commit();

    const int a_row = lane & 15, a_half = lane >> 4;
    const int bg = lane >> 3, b_nrow = (bg >> 1) * 8 + (lane & 7), b_half = bg & 1;
    uint32_t aq[2][8][4];

    for (int tt = 0; tt < nt; tt++) {
        int t0 = tt * 64;
        if (tt + 1 < nt) {
            uint32_t kb = sb + FS_K_OFF + (uint32_t)(((tt + 1) & 1) * (64 * 272));
            #pragma unroll
            for (int i = 0; i < 4; i++) {
                int q = tid + 256 * i;
                int r = q >> 4, seg = q & 15;
                cp_async16(kb + (uint32_t)(r * 272 + seg * 16),
                           Kp + (size_t)(t0 + 64 + r) * DKH + seg * 4);
            }
            cp_commit();
            cp_wait<1>();
        } else {
            cp_wait<0>();
        }
        __syncthreads();

        if (tt == 0) {   // preload + convert Q fragments once
            #pragma unroll
            for (int mi = 0; mi < 2; mi++)
                #pragma unroll
                for (int kk = 0; kk < 8; kk++) {
                    ldsm_x4(aq[mi][kk][0], aq[mi][kk][1], aq[mi][kk][2], aq[mi][kk][3],
                            qb + (uint32_t)((wm * 32 + mi * 16 + a_row) * 272
                                            + a_half * 16 + kk * 32));
                    #pragma unroll
                    for (int j = 0; j < 4; j++) aq[mi][kk][j] = f2tf32(aq[mi][kk][j]);
                }
        }

        uint32_t kb = sb + FS_K_OFF + (uint32_t)((tt & 1) * (64 * 272));
        float acc[2][2][4] = {};
        #pragma unroll
        for (int kk = 0; kk < 8; kk++) {
            uint32_t b[2][2];
            {
                uint32_t r0, r1, r2, r3;
                ldsm_x4(r0, r1, r2, r3,
                        kb + (uint32_t)((wn * 16 + b_nrow) * 272 + b_half * 16 + kk * 32));
                b[0][0] = f2tf32(r0); b[0][1] = f2tf32(r1);
                b[1][0] = f2tf32(r2); b[1][1] = f2tf32(r3);
            }
            #pragma unroll
            for (int mi = 0; mi < 2; mi++)
                #pragma unroll
                for (int ni = 0; ni < 2; ni++)
                    mma_tf32(acc[mi][ni], aq[mi][kk], b[ni]);
        }

        // fragment -> smem scores with scale + rel_bias
        #pragma unroll
        for (int mi = 0; mi < 2; mi++) {
            int r = wm * 32 + mi * 16 + (lane >> 2);
            #pragma unroll
            for (int ni = 0; ni < 2; ni++) {
                int t = t0 + wn * 16 + ni * 8 + (lane & 3) * 2;
                sc[r * FS_SCS + t]           = acc[mi][ni][0] * 0.125f + rb[(size_t)(s0 + r) * SEQ + t];
                sc[r * FS_SCS + t + 1]       = acc[mi][ni][1] * 0.125f + rb[(size_t)(s0 + r) * SEQ + t + 1];
                sc[(r + 8) * FS_SCS + t]     = acc[mi][ni][2] * 0.125f + rb[(size_t)(s0 + r + 8) * SEQ + t];
                sc[(r + 8) * FS_SCS + t + 1] = acc[mi][ni][3] * 0.125f + rb[(size_t)(s0 + r + 8) * SEQ + t + 1];
            }
        }
        __syncthreads();
    }

    // ---- causal softmax in smem; write probs [0, s0+64) per row ----
    const int tcap = s0 + 64, tcap4 = tcap >> 2;
    for (int rr = 0; rr < 8; rr++) {
        int row = wid * 8 + rr;
        int s = s0 + row;
        float* srow = sc + row * FS_SCS;
        int n = s + 1;

        float mx = -INFINITY;
        for (int t = lane; t < n; t += 32) mx = fmaxf(mx, srow[t]);
        #pragma unroll
        for (int o = 16; o; o >>= 1) mx = fmaxf(mx, __shfl_xor_sync(0xffffffffu, mx, o));

        float sum = 0.f;
        for (int t = lane; t < n; t += 32) {
            float e = __expf(srow[t] - mx);
            srow[t] = e;
            sum += e;
        }
        #pragma unroll
        for (int o = 16; o; o >>= 1) sum += __shfl_xor_sync(0xffffffffu, sum, o);

        for (int t = n + lane; t < tcap; t += 32) srow[t] = 0.f;
        float inv = 1.0f / sum;
        __syncwarp();

        for (int q4 = lane; q4 < tcap4; q4 += 32) {
            float4 v = *(float4*)&srow[q4 * 4];
            v.x *= inv; v.y *= inv; v.z *= inv; v.w *= inv;
            *(float4*)&Pp[(size_t)s * SEQ + q4 * 4] = v;
        }
        __syncwarp();
    }
}

// ---------------------------------------------------------------------------
// ctx (tf32 mma): C[s][d] = sum_t P[s][t] * Vt[d][t], truncated at s0+64.
// ---------------------------------------------------------------------------
#define CX_V_OFF (2 * 64 * 272)      // 34816
#define CX_SMEM  (4 * 64 * 272)      // 69632

__global__ void __launch_bounds__(256)
attn_ctx_tc()
{
    extern __shared__ char sm[];
    const uint32_t sb = smem_u32(sm);

    const int bh = blockIdx.x, st = blockIdx.y;
    const int b = bh >> 4, h = bh & 15;
    const int s0 = st * 64, nc = st + 1;

    const float* Pp = g_P  + (size_t)bh * SEQ * SEQ;
    const float* Vp = g_Vt + (size_t)bh * DKH * SEQ;

    const int tid = threadIdx.x, wid = tid >> 5, lane = tid & 31;
    const int wm = wid >> 2, wn = wid & 3;
    const int a_row = lane & 15, a_half = lane >> 4;
    const int bg = lane >> 3, b_nrow = (bg >> 1) * 8 + (lane & 7), b_half = bg & 1;

    auto load = [&](int c) {
        uint32_t pb = sb + (uint32_t)((c & 1) * (64 * 272));
        uint32_t vb = sb + CX_V_OFF + (uint32_t)((c & 1) * (64 * 272));
        #pragma unroll
        for (int i = 0; i < 4; i++) {
            int q = tid + 256 * i;
            int r = q >> 4, seg = q & 15;
            cp_async16(pb + (uint32_t)(r * 272 + seg * 16),
                       Pp + (size_t)(s0 + r) * SEQ + c * 64 + seg * 4);
            cp_async16(vb + (uint32_t)(r * 272 + seg * 16),
                       Vp + (size_t)r * SEQ + c * 64 + seg * 4);
        }
        cp_commit();
    };

    load(0);
    float acc[2][2][4] = {};
    for (int c = 0; c < nc; c++) {
        if (c + 1 < nc) { load(c + 1); cp_wait<1>(); } else cp_wait<0>();
        __syncthreads();
        uint32_t pb = sb + (uint32_t)((c & 1) * (64 * 272));
        uint32_t vb = sb + CX_V_OFF + (uint32_t)((c & 1) * (64 * 272));
        #pragma unroll
        for (int kk = 0; kk < 8; kk++) {
            uint32_t a[2][4], bb[2][2];
            #pragma unroll
            for (int mi = 0; mi < 2; mi++) {
                ldsm_x4(a[mi][0], a[mi][1], a[mi][2], a[mi][3],
                        pb + (uint32_t)((wm * 32 + mi * 16 + a_row) * 272
                                        + a_half * 16 + kk * 32));
                #pragma unroll
                for (int j = 0; j < 4; j++) a[mi][j] = f2tf32(a[mi][j]);
            }
            {
                uint32_t r0, r1, r2, r3;
                ldsm_x4(r0, r1, r2, r3,
                        vb + (uint32_t)((wn * 16 + b_nrow) * 272 + b_half * 16 + kk * 32));
                bb[0][0] = f2tf32(r0); bb[0][1] = f2tf32(r1);
                bb[1][0] = f2tf32(r2); bb[1][1] = f2tf32(r3);
            }
            #pragma unroll
            for (int mi = 0; mi < 2; mi++)
                #pragma unroll
                for (int ni = 0; ni < 2; ni++)
                    mma_tf32(acc[mi][ni], a[mi], bb[ni]);
        }
        __syncthreads();
    }

    #pragma unroll
    for (int mi = 0; mi < 2; mi++) {
        int r = wm * 32 + mi * 16 + (lane >> 2);
        #pragma unroll
        for (int ni = 0; ni < 2; ni++) {
            int cc = wn * 16 + ni * 8 + (lane & 3) * 2;
            size_t o = ((size_t)(b * SEQ) + s0 + r) * DM + h * DKH + cc;
            *(float2*)&g_C[o]          = make_float2(acc[mi][ni][0], acc[mi][ni][1]);
            *(float2*)&g_C[o + 8 * DM] = make_float2(acc[mi][ni][2], acc[mi][ni][3]);
        }
    }
}

// ---------------------------------------------------------------------------
// attn_mean[b,s,t] = (1/16) * sum_h P[b,h,s,t] ; exact 0 for t > s (causal)
// ---------------------------------------------------------------------------
__global__ void __launch_bounds__(256) attn_mean_kernel(float* __restrict__ outp)
{
    size_t idx = (size_t)blockIdx.x * 256 + threadIdx.x;
    int t = (int)(idx & 511);
    int s = (int)((idx >> 9) & 511);
    int b = (int)(idx >> 18);
    if (t > s) { outp[idx] = 0.f; return; }
    const float* base = g_P + ((size_t)(b * NH) * SEQ + s) * SEQ + t;
    float sum = 0.f;
    #pragma unroll
    for (int h = 0; h < NH; h++) sum += base[(size_t)h * SEQ * SEQ];
    outp[idx] = sum * (1.0f / 16.0f);
}

// ---------------------------------------------------------------------------
// Launch
// ---------------------------------------------------------------------------
extern "C" void kernel_launch(void* const* d_in, const int* in_sizes, int n_in,
                              void* d_out, int out_size)
{
    const float* query    = (const float*)d_in[0];
    const float* key      = (const float*)d_in[1];
    const float* value    = (const float*)d_in[2];
    const float* wq_w     = (const float*)d_in[3];
    const float* wq_b     = (const float*)d_in[4];
    const float* wk_w     = (const float*)d_in[5];
    const float* wk_b     = (const float*)d_in[6];
    const float* wv_w     = (const float*)d_in[7];
    const float* wv_b     = (const float*)d_in[8];
    const float* wo_w     = (const float*)d_in[9];
    const float* wo_b     = (const float*)d_in[10];
    const float* rel_bias = (const float*)d_in[11];

    float* out       = (float*)d_out;
    float* attn_mean = out + (size_t)BQ * SEQ * DM;

    static int smem_set = 0;
    if (!smem_set) {
        cudaFuncSetAttribute(gemm_tc,     cudaFuncAttributeMaxDynamicSharedMemorySize, SMEM_DYN);
        cudaFuncSetAttribute(attn_fused,  cudaFuncAttributeMaxDynamicSharedMemorySize, FS_SMEM);
        cudaFuncSetAttribute(attn_ctx_tc, cudaFuncAttributeMaxDynamicSharedMemorySize, CX_SMEM);
        smem_set = 1;
    }

    dim3 gG(DM / 128, MROWS / 128);          // (8, 64)

    gemm_tc<<<gG, 256, SMEM_DYN>>>(query, wq_w, wq_b, nullptr, 0);   // -> g_Q
    gemm_tc<<<gG, 256, SMEM_DYN>>>(key,   wk_w, wk_b, nullptr, 1);   // -> g_K
    gemm_tc<<<gG, 256, SMEM_DYN>>>(value, wv_w, wv_b, nullptr, 2);   // -> g_Vt (transposed)

    attn_fused<<<dim3(BQ * NH, 8), 256, FS_SMEM>>>(rel_bias);
    attn_ctx_tc<<<dim3(BQ * NH, 8), 256, CX_SMEM>>>();
    attn_mean_kernel<<<(BQ * SEQ * SEQ) / 256, 256>>>(attn_mean);

    gemm_tc<<<gG, 256, SMEM_DYN>>>(nullptr, wo_w, wo_b, out, 3);     // g_C -> out
}

// round 13
// speedup vs baseline: 3.2095x; 1.0840x over previous
#include <cuda_runtime.h>
#include <math.h>
#include <stdint.h>

// Problem constants
#define BQ   16
#define SEQ  512
#define NH   16
#define DKH  64
#define DM   1024
#define MROWS (BQ * SEQ)   // 8192

// ---------------------------------------------------------------------------
// Scratch (device globals; allocation-free per harness rules)
// ---------------------------------------------------------------------------
__device__ float g_Q[BQ * NH * SEQ * DKH];            // [b][h][s][d]
__device__ float g_K[BQ * NH * SEQ * DKH];            // [b][h][t][d]
__device__ float g_Vt[BQ * NH * DKH * SEQ];           // [b][h][d][t]  (transposed V)
__device__ float g_P[(size_t)BQ * NH * SEQ * SEQ];    // [b][h][s][t]  probs (lower tri)
__device__ float g_C[BQ * SEQ * DM];                  // [b][s][h*64+d]

// ---------------------------------------------------------------------------
// PTX helpers (base-target legal: sm_80+ features only)
// ---------------------------------------------------------------------------
__device__ __forceinline__ uint32_t smem_u32(const void* p) {
    return (uint32_t)__cvta_generic_to_shared((void*)p);
}
__device__ __forceinline__ void cp_async16(uint32_t dst, const void* src) {
    asm volatile("cp.async.cg.shared.global [%0], [%1], 16;" :: "r"(dst), "l"(src));
}
__device__ __forceinline__ void cp_commit() {
    asm volatile("cp.async.commit_group;" ::: "memory");
}
template <int N> __device__ __forceinline__ void cp_wait() {
    asm volatile("cp.async.wait_group %0;" :: "n"(N) : "memory");
}
__device__ __forceinline__ void ldsm_x4(uint32_t& r0, uint32_t& r1, uint32_t& r2,
                                        uint32_t& r3, uint32_t addr) {
    asm volatile("ldmatrix.sync.aligned.m8n8.x4.shared.b16 {%0,%1,%2,%3}, [%4];"
                 : "=r"(r0), "=r"(r1), "=r"(r2), "=r"(r3) : "r"(addr));
}
__device__ __forceinline__ uint32_t f2tf32(uint32_t x) {
    uint32_t y;
    asm("cvt.rna.tf32.f32 %0, %1;" : "=r"(y) : "f"(__uint_as_float(x)));
    return y;
}
__device__ __forceinline__ void mma_tf32(float* c, const uint32_t* a, const uint32_t* b) {
    asm volatile(
        "mma.sync.aligned.m16n8k8.row.col.f32.tf32.tf32.f32 "
        "{%0,%1,%2,%3}, {%4,%5,%6,%7}, {%8,%9}, {%0,%1,%2,%3};"
        : "+f"(c[0]), "+f"(c[1]), "+f"(c[2]), "+f"(c[3])
        : "r"(a[0]), "r"(a[1]), "r"(a[2]), "r"(a[3]), "r"(b[0]), "r"(b[1]));
}

// ---------------------------------------------------------------------------
// tf32 mma.sync GEMM: C = A @ W^T + bias; M=8192, N=1024, K=1024
// Tile 128x128, K-chunk 32, 3-stage cp.async pipeline, 2 CTAs/SM.
// mode 0/1: head-layout to g_Q/g_K ; mode 2: TRANSPOSED to g_Vt ; mode 3: g_C -> C_ext
// ---------------------------------------------------------------------------
#define KC     32
#define NSTG   3
#define ROWB   144                      // bytes per smem row (36 floats)
#define ASTG   (128 * ROWB)             // 18432 B per matrix per stage
#define STGB   (2 * ASTG)               // 36864 B per stage
#define SMEM_DYN (NSTG * STGB)          // 110592 B
#define EPS    133                      // epilogue smem row stride (floats)

__global__ void __launch_bounds__(256, 2)
gemm_tc(const float* __restrict__ A_ext, const float* __restrict__ W,
        const float* __restrict__ bias, float* __restrict__ C_ext, int mode)
{
    extern __shared__ char smem_raw[];
    __shared__ float bias_s[128];
    const uint32_t sb = smem_u32(smem_raw);

    const float* A = (mode == 3) ? g_C : A_ext;
    const int tid  = threadIdx.x;
    const int wid  = tid >> 5, lane = tid & 31;
    const int wm   = wid >> 2, wn = wid & 3;          // warp grid 2 x 4
    const int m0   = blockIdx.y * 128, n0 = blockIdx.x * 128;

    if (tid < 128) bias_s[tid] = bias[n0 + tid];

    float acc[4][4][4] = {};                          // [mi][ni][reg]

    auto load_chunk = [&](int c) {
        uint32_t base = sb + (uint32_t)(c % NSTG) * STGB;
        const float* Ag = A + (size_t)m0 * DM + c * KC;
        const float* Wg = W + (size_t)n0 * DM + c * KC;
        #pragma unroll
        for (int i = 0; i < 4; i++) {
            int q = tid + 256 * i;                    // 0..1023
            int r = q >> 3, c16 = q & 7;              // row, 16B segment
            uint32_t dst = base + (uint32_t)(r * ROWB + c16 * 16);
            cp_async16(dst,        (const char*)(Ag + (size_t)r * DM) + c16 * 16);
            cp_async16(dst + ASTG, (const char*)(Wg + (size_t)r * DM) + c16 * 16);
        }
    };

    load_chunk(0); cp_commit();
    load_chunk(1); cp_commit();

    const int a_row  = lane & 15;
    const int a_half = (lane >> 4) & 1;
    const uint32_t a_off0 = (uint32_t)((wm * 64 + a_row) * ROWB + a_half * 16);
    const int bg     = lane >> 3;
    const int b_nrow = (bg >> 1) * 8 + (lane & 7);
    const int b_half = bg & 1;
    const uint32_t b_off0 = (uint32_t)(ASTG + (wn * 32 + b_nrow) * ROWB + b_half * 16);

    const int NCH = DM / KC;                          // 32
    for (int c = 0; c < NCH; c++) {
        cp_wait<1>();
        __syncthreads();
        uint32_t base = sb + (uint32_t)(c % NSTG) * STGB;

        #pragma unroll
        for (int kk = 0; kk < 4; kk++) {
            uint32_t a[4][4], b[4][2];
            #pragma unroll
            for (int mi = 0; mi < 4; mi++)
                ldsm_x4(a[mi][0], a[mi][1], a[mi][2], a[mi][3],
                        base + a_off0 + (uint32_t)(mi * 16 * ROWB + kk * 32));
            #pragma unroll
            for (int np = 0; np < 2; np++) {
                uint32_t r0, r1, r2, r3;
                ldsm_x4(r0, r1, r2, r3,
                        base + b_off0 + (uint32_t)(np * 16 * ROWB + kk * 32));
                b[np * 2][0] = r0;     b[np * 2][1] = r1;
                b[np * 2 + 1][0] = r2; b[np * 2 + 1][1] = r3;
            }
            #pragma unroll
            for (int mi = 0; mi < 4; mi++)
                #pragma unroll
                for (int j = 0; j < 4; j++) a[mi][j] = f2tf32(a[mi][j]);
            #pragma unroll
            for (int ni = 0; ni < 4; ni++) {
                b[ni][0] = f2tf32(b[ni][0]);
                b[ni][1] = f2tf32(b[ni][1]);
            }
            #pragma unroll
            for (int mi = 0; mi < 4; mi++)
                #pragma unroll
                for (int ni = 0; ni < 4; ni++)
                    mma_tf32(acc[mi][ni], a[mi], b[ni]);
        }

        int cn = c + 2;
        if (cn < NCH) load_chunk(cn);
        cp_commit();                                  // one group per iteration
    }

    // ---------------- epilogue: regs -> smem -> coalesced gmem -------------
    __syncthreads();
    float* smemT = (float*)smem_raw;                  // 128 x EPS floats
    {
        const int r0 = wm * 64 + (lane >> 2);
        const int cc0 = wn * 32 + 2 * (lane & 3);
        #pragma unroll
        for (int mi = 0; mi < 4; mi++) {
            #pragma unroll
            for (int ni = 0; ni < 4; ni++) {
                int r = r0 + mi * 16, cc = cc0 + ni * 8;
                smemT[r * EPS + cc]           = acc[mi][ni][0];
                smemT[r * EPS + cc + 1]       = acc[mi][ni][1];
                smemT[(r + 8) * EPS + cc]     = acc[mi][ni][2];
                smemT[(r + 8) * EPS + cc + 1] = acc[mi][ni][3];
            }
        }
    }
    __syncthreads();

    const int bq = m0 >> 9, s_base = m0 & 511;
    if (mode == 2) {
        // transposed store: g_Vt[b][h][d][t]
        #pragma unroll
        for (int i = 0; i < 16; i++) {
            int q = tid + 256 * i;                    // 0..4095
            int cc = q >> 5;                          // n-col 0..127
            int sc4 = (q & 31) * 4;                   // s-chunk
            float4 v;
            v.x = smemT[(sc4 + 0) * EPS + cc] + bias_s[cc];
            v.y = smemT[(sc4 + 1) * EPS + cc] + bias_s[cc];
            v.z = smemT[(sc4 + 2) * EPS + cc] + bias_s[cc];
            v.w = smemT[(sc4 + 3) * EPS + cc] + bias_s[cc];
            int n = n0 + cc;
            int h = n >> 6, d = n & 63;
            *(float4*)(g_Vt + ((size_t)(bq * NH + h) * DKH + d) * SEQ + s_base + sc4) = v;
        }
    } else if (mode < 2) {
        float* Cq = (mode == 0) ? g_Q : g_K;
        #pragma unroll
        for (int i = 0; i < 16; i++) {
            int q = tid + 256 * i;
            int r = q >> 5, c4 = (q & 31) * 4;
            float4 v;
            v.x = smemT[r * EPS + c4 + 0] + bias_s[c4 + 0];
            v.y = smemT[r * EPS + c4 + 1] + bias_s[c4 + 1];
            v.z = smemT[r * EPS + c4 + 2] + bias_s[c4 + 2];
            v.w = smemT[r * EPS + c4 + 3] + bias_s[c4 + 3];
            int n = n0 + c4;
            int h = n >> 6, db = n & 63;
            *(float4*)(Cq + ((size_t)(bq * NH + h) * SEQ + s_base + r) * DKH + db) = v;
        }
    } else {
        #pragma unroll
        for (int i = 0; i < 16; i++) {
            int q = tid + 256 * i;
            int r = q >> 5, c4 = (q & 31) * 4;
            float4 v;
            v.x = smemT[r * EPS + c4 + 0] + bias_s[c4 + 0];
            v.y = smemT[r * EPS + c4 + 1] + bias_s[c4 + 1];
            v.z = smemT[r * EPS + c4 + 2] + bias_s[c4 + 2];
            v.w = smemT[r * EPS + c4 + 3] + bias_s[c4 + 3];
            *(float4*)(C_ext + (size_t)(m0 + r) * DM + n0 + c4) = v;
        }
    }
}

// ---------------------------------------------------------------------------
// FULLY FUSED attention: scores + bias + causal softmax + P-write + ctx.
//   block = (bh, s-tile of 32 rows). Score strip (32 x nt*64) lives in smem;
//   softmax in place (normalized back to smem); ctx = P @ V^T from the strip.
//   ~107 KB smem -> 2 CTAs/SM. Heavy tiles scheduled first.
// ---------------------------------------------------------------------------
#define TS       32                           // s rows per block
#define SCS      516                          // strip row stride (floats)
#define F_Q_OFF  (TS * SCS * 4)               // 66048
#define F_K_OFF  (F_Q_OFF + TS * 272)         // 74752
#define F_SMEM   (F_K_OFF + 2 * 64 * 272)     // 109568

__global__ void __launch_bounds__(256, 2)
attn_fused(const float* __restrict__ rel_bias)
{
    extern __shared__ char sm[];
    float* sc = (float*)sm;
    const uint32_t sb = smem_u32(sm);
    const uint32_t qb = sb + F_Q_OFF;

    const int bh = blockIdx.x;
    const int st = 15 - blockIdx.y;           // heavy tiles first
    const int h  = bh & 15, b = bh >> 4;
    const int s0 = st * TS;
    const int nt = (st >> 1) + 1;             // 64-wide t tiles
    const int tcap64 = nt * 64;

    const float* Qp = g_Q  + (size_t)bh * SEQ * DKH;
    const float* Kp = g_K  + (size_t)bh * SEQ * DKH;
    const float* Vp = g_Vt + (size_t)bh * DKH * SEQ;
    const float* rb = rel_bias + (size_t)h * SEQ * SEQ;
    float* Pp = g_P + (size_t)bh * SEQ * SEQ;

    const int tid = threadIdx.x, wid = tid >> 5, lane = tid & 31;
    const int wm = wid >> 2, wn = wid & 3;    // 2 x 4 warps; warp tile 16x16

    // group 0: Q tile (32x64) + K tile 0 (64x64)
    #pragma unroll
    for (int i = 0; i < 2; i++) {
        int q = tid + 256 * i;
        int r = q >> 4, seg = q & 15;
        cp_async16(qb + (uint32_t)(r * 272 + seg * 16),
                   Qp + (size_t)(s0 + r) * DKH + seg * 4);
    }
    #pragma unroll
    for (int i = 0; i < 4; i++) {
        int q = tid + 256 * i;
        int r = q >> 4, seg = q & 15;
        cp_async16(sb + F_K_OFF + (uint32_t)(r * 272 + seg * 16),
                   Kp + (size_t)r * DKH + seg * 4);
    }
    cp_commit();

    const int a_row = lane & 15, a_half = lane >> 4;
    const int bg = lane >> 3, b_nrow = (bg >> 1) * 8 + (lane & 7), b_half = bg & 1;
    uint32_t aq[8][4];

    // ---------------- phase 1: scores -> smem strip -------------------------
    for (int tt = 0; tt < nt; tt++) {
        int t0 = tt * 64;
        if (tt + 1 < nt) {
            uint32_t kb = sb + F_K_OFF + (uint32_t)(((tt + 1) & 1) * (64 * 272));
            #pragma unroll
            for (int i = 0; i < 4; i++) {
                int q = tid + 256 * i;
                int r = q >> 4, seg = q & 15;
                cp_async16(kb + (uint32_t)(r * 272 + seg * 16),
                           Kp + (size_t)(t0 + 64 + r) * DKH + seg * 4);
            }
            cp_commit();
            cp_wait<1>();
        } else {
            cp_wait<0>();
        }
        __syncthreads();

        if (tt == 0) {   // preload + convert Q fragments once
            #pragma unroll
            for (int kk = 0; kk < 8; kk++) {
                ldsm_x4(aq[kk][0], aq[kk][1], aq[kk][2], aq[kk][3],
                        qb + (uint32_t)((wm * 16 + a_row) * 272 + a_half * 16 + kk * 32));
                #pragma unroll
                for (int j = 0; j < 4; j++) aq[kk][j] = f2tf32(aq[kk][j]);
            }
        }

        uint32_t kb = sb + F_K_OFF + (uint32_t)((tt & 1) * (64 * 272));
        float acc[2][4] = {};
        #pragma unroll
        for (int kk = 0; kk < 8; kk++) {
            uint32_t bb[2][2];
            {
                uint32_t r0, r1, r2, r3;
                ldsm_x4(r0, r1, r2, r3,
                        kb + (uint32_t)((wn * 16 + b_nrow) * 272 + b_half * 16 + kk * 32));
                bb[0][0] = f2tf32(r0); bb[0][1] = f2tf32(r1);
                bb[1][0] = f2tf32(r2); bb[1][1] = f2tf32(r3);
            }
            mma_tf32(acc[0], aq[kk], bb[0]);
            mma_tf32(acc[1], aq[kk], bb[1]);
        }

        {
            int r = wm * 16 + (lane >> 2);
            #pragma unroll
            for (int ni = 0; ni < 2; ni++) {
                int t = t0 + wn * 16 + ni * 8 + (lane & 3) * 2;
                sc[r * SCS + t]           = acc[ni][0] * 0.125f + rb[(size_t)(s0 + r) * SEQ + t];
                sc[r * SCS + t + 1]       = acc[ni][1] * 0.125f + rb[(size_t)(s0 + r) * SEQ + t + 1];
                sc[(r + 8) * SCS + t]     = acc[ni][2] * 0.125f + rb[(size_t)(s0 + r + 8) * SEQ + t];
                sc[(r + 8) * SCS + t + 1] = acc[ni][3] * 0.125f + rb[(size_t)(s0 + r + 8) * SEQ + t + 1];
            }
        }
        __syncthreads();
    }

    // kick V tile 0 load (overlaps with softmax); K buffers are free now
    {
        uint32_t vb = sb + F_K_OFF;
        #pragma unroll
        for (int i = 0; i < 4; i++) {
            int q = tid + 256 * i;
            int r = q >> 4, seg = q & 15;
            cp_async16(vb + (uint32_t)(r * 272 + seg * 16),
                       Vp + (size_t)r * SEQ + seg * 4);
        }
        cp_commit();
    }

    // ---------------- phase 2: causal softmax in smem + P write -------------
    const int tcap4 = tcap64 >> 2;
    #pragma unroll
    for (int rr = 0; rr < 4; rr++) {
        int row = wid * 4 + rr;
        int s = s0 + row;
        float* srow = sc + row * SCS;
        int n = s + 1;

        float mx = -INFINITY;
        for (int t = lane; t < n; t += 32) mx = fmaxf(mx, srow[t]);
        #pragma unroll
        for (int o = 16; o; o >>= 1) mx = fmaxf(mx, __shfl_xor_sync(0xffffffffu, mx, o));

        float sum = 0.f;
        for (int t = lane; t < n; t += 32) {
            float e = __expf(srow[t] - mx);
            srow[t] = e;
            sum += e;
        }
        #pragma unroll
        for (int o = 16; o; o >>= 1) sum += __shfl_xor_sync(0xffffffffu, sum, o);

        for (int t = n + lane; t < tcap64; t += 32) srow[t] = 0.f;
        float inv = 1.0f / sum;
        __syncwarp();

        for (int q4 = lane; q4 < tcap4; q4 += 32) {
            float4 v = *(float4*)&srow[q4 * 4];
            v.x *= inv; v.y *= inv; v.z *= inv; v.w *= inv;
            *(float4*)&srow[q4 * 4] = v;                       // normalized in smem
            *(float4*)&Pp[(size_t)s * SEQ + q4 * 4] = v;       // and to gmem
        }
        __syncwarp();
    }
    __syncthreads();

    // ---------------- phase 3: ctx = P @ V^T from the strip -----------------
    float accc[2][4] = {};
    for (int c = 0; c < nt; c++) {
        if (c + 1 < nt) {
            uint32_t vb = sb + F_K_OFF + (uint32_t)(((c + 1) & 1) * (64 * 272));
            #pragma unroll
            for (int i = 0; i < 4; i++) {
                int q = tid + 256 * i;
                int r = q >> 4, seg = q & 15;
                cp_async16(vb + (uint32_t)(r * 272 + seg * 16),
                           Vp + (size_t)r * SEQ + (c + 1) * 64 + seg * 4);
            }
            cp_commit();
            cp_wait<1>();
        } else {
            cp_wait<0>();
        }
        __syncthreads();

        uint32_t vb = sb + F_K_OFF + (uint32_t)((c & 1) * (64 * 272));
        #pragma unroll
        for (int kk = 0; kk < 8; kk++) {
            uint32_t a[4], bb[2][2];
            ldsm_x4(a[0], a[1], a[2], a[3],
                    sb + (uint32_t)((wm * 16 + a_row) * (SCS * 4) + c * 256
                                    + a_half * 16 + kk * 32));
            #pragma unroll
            for (int j = 0; j < 4; j++) a[j] = f2tf32(a[j]);
            {
                uint32_t r0, r1, r2, r3;
                ldsm_x4(r0, r1, r2, r3,
                        vb + (uint32_t)((wn * 16 + b_nrow) * 272 + b_half * 16 + kk * 32));
                bb[0][0] = f2tf32(r0); bb[0][1] = f2tf32(r1);
                bb[1][0] = f2tf32(r2); bb[1][1] = f2tf32(r3);
            }
            mma_tf32(accc[0], a, bb[0]);
            mma_tf32(accc[1], a, bb[1]);
        }
        __syncthreads();
    }

    {
        int r = wm * 16 + (lane >> 2);
        #pragma unroll
        for (int ni = 0; ni < 2; ni++) {
            int cc = wn * 16 + ni * 8 + (lane & 3) * 2;
            size_t o = ((size_t)(b * SEQ) + s0 + r) * DM + h * DKH + cc;
            *(float2*)&g_C[o]          = make_float2(accc[ni][0], accc[ni][1]);
            *(float2*)&g_C[o + 8 * DM] = make_float2(accc[ni][2], accc[ni][3]);
        }
    }
}

// ---------------------------------------------------------------------------
// attn_mean[b,s,t] = (1/16) * sum_h P[b,h,s,t] ; exact 0 for t > s (causal)
// ---------------------------------------------------------------------------
__global__ void __launch_bounds__(256) attn_mean_kernel(float* __restrict__ outp)
{
    size_t idx = (size_t)blockIdx.x * 256 + threadIdx.x;
    int t = (int)(idx & 511);
    int s = (int)((idx >> 9) & 511);
    int b = (int)(idx >> 18);
    if (t > s) { outp[idx] = 0.f; return; }
    const float* base = g_P + ((size_t)(b * NH) * SEQ + s) * SEQ + t;
    float sum = 0.f;
    #pragma unroll
    for (int h = 0; h < NH; h++) sum += base[(size_t)h * SEQ * SEQ];
    outp[idx] = sum * (1.0f / 16.0f);
}

// ---------------------------------------------------------------------------
// Launch
// ---------------------------------------------------------------------------
extern "C" void kernel_launch(void* const* d_in, const int* in_sizes, int n_in,
                              void* d_out, int out_size)
{
    const float* query    = (const float*)d_in[0];
    const float* key      = (const float*)d_in[1];
    const float* value    = (const float*)d_in[2];
    const float* wq_w     = (const float*)d_in[3];
    const float* wq_b     = (const float*)d_in[4];
    const float* wk_w     = (const float*)d_in[5];
    const float* wk_b     = (const float*)d_in[6];
    const float* wv_w     = (const float*)d_in[7];
    const float* wv_b     = (const float*)d_in[8];
    const float* wo_w     = (const float*)d_in[9];
    const float* wo_b     = (const float*)d_in[10];
    const float* rel_bias = (const float*)d_in[11];

    float* out       = (float*)d_out;
    float* attn_mean = out + (size_t)BQ * SEQ * DM;

    static int smem_set = 0;
    if (!smem_set) {
        cudaFuncSetAttribute(gemm_tc,    cudaFuncAttributeMaxDynamicSharedMemorySize, SMEM_DYN);
        cudaFuncSetAttribute(attn_fused, cudaFuncAttributeMaxDynamicSharedMemorySize, F_SMEM);
        smem_set = 1;
    }

    dim3 gG(DM / 128, MROWS / 128);          // (8, 64)

    gemm_tc<<<gG, 256, SMEM_DYN>>>(query, wq_w, wq_b, nullptr, 0);   // -> g_Q
    gemm_tc<<<gG, 256, SMEM_DYN>>>(key,   wk_w, wk_b, nullptr, 1);   // -> g_K
    gemm_tc<<<gG, 256, SMEM_DYN>>>(value, wv_w, wv_b, nullptr, 2);   // -> g_Vt (transposed)

    attn_fused<<<dim3(BQ * NH, 16), 256, F_SMEM>>>(rel_bias);
    attn_mean_kernel<<<(BQ * SEQ * SEQ) / 256, 256>>>(attn_mean);

    gemm_tc<<<gG, 256, SMEM_DYN>>>(nullptr, wo_w, wo_b, out, 3);     // g_C -> out
}

// round 16
// speedup vs baseline: 3.4546x; 1.0764x over previous
#include <cuda_runtime.h>
#include <math.h>
#include <stdint.h>

// Problem constants
#define BQ   16
#define SEQ  512
#define NH   16
#define DKH  64
#define DM   1024
#define MROWS (BQ * SEQ)   // 8192

// ---------------------------------------------------------------------------
// Scratch (device globals; allocation-free per harness rules)
// ---------------------------------------------------------------------------
__device__ float g_Q[BQ * NH * SEQ * DKH];            // [b][h][s][d]   (tf32-rounded)
__device__ float g_K[BQ * NH * SEQ * DKH];            // [b][h][t][d]   (tf32-rounded)
__device__ float g_Vt[BQ * NH * DKH * SEQ];           // [b][h][d][t]   (tf32-rounded)
__device__ float g_P[(size_t)BQ * NH * SEQ * SEQ];    // [b][h][s][t]   probs (lower tri)
__device__ float g_C[BQ * SEQ * DM];                  // [b][s][h*64+d]

// ---------------------------------------------------------------------------
// PTX helpers (base-target legal: sm_80+ features only)
// ---------------------------------------------------------------------------
__device__ __forceinline__ uint32_t smem_u32(const void* p) {
    return (uint32_t)__cvta_generic_to_shared((void*)p);
}
__device__ __forceinline__ void cp_async16(uint32_t dst, const void* src) {
    asm volatile("cp.async.cg.shared.global [%0], [%1], 16;" :: "r"(dst), "l"(src));
}
__device__ __forceinline__ void cp_commit() {
    asm volatile("cp.async.commit_group;" ::: "memory");
}
template <int N> __device__ __forceinline__ void cp_wait() {
    asm volatile("cp.async.wait_group %0;" :: "n"(N) : "memory");
}
__device__ __forceinline__ void ldsm_x4(uint32_t& r0, uint32_t& r1, uint32_t& r2,
                                        uint32_t& r3, uint32_t addr) {
    asm volatile("ldmatrix.sync.aligned.m8n8.x4.shared.b16 {%0,%1,%2,%3}, [%4];"
                 : "=r"(r0), "=r"(r1), "=r"(r2), "=r"(r3) : "r"(addr));
}
__device__ __forceinline__ uint32_t f2tf32(uint32_t x) {
    uint32_t y;
    asm("cvt.rna.tf32.f32 %0, %1;" : "=r"(y) : "f"(__uint_as_float(x)));
    return y;
}
__device__ __forceinline__ float f2tf32f(float x) {
    uint32_t y;
    asm("cvt.rna.tf32.f32 %0, %1;" : "=r"(y) : "f"(x));
    return __uint_as_float(y);
}
__device__ __forceinline__ void mma_tf32(float* c, const uint32_t* a, const uint32_t* b) {
    asm volatile(
        "mma.sync.aligned.m16n8k8.row.col.f32.tf32.tf32.f32 "
        "{%0,%1,%2,%3}, {%4,%5,%6,%7}, {%8,%9}, {%0,%1,%2,%3};"
        : "+f"(c[0]), "+f"(c[1]), "+f"(c[2]), "+f"(c[3])
        : "r"(a[0]), "r"(a[1]), "r"(a[2]), "r"(a[3]), "r"(b[0]), "r"(b[1]));
}

// ---------------------------------------------------------------------------
// tf32 mma.sync GEMM: C = A @ W^T + bias; M=8192, N=1024, K=1024
// Tile 128x128, K-chunk 32, 3-stage cp.async pipeline, 2 CTAs/SM.
// mode = mode_base + blockIdx.z:
//   0/1: head-layout to g_Q/g_K (tf32-rounded)
//   2  : TRANSPOSED to g_Vt (tf32-rounded)
//   3  : g_C -> C_ext (full precision)
// ---------------------------------------------------------------------------
#define KC     32
#define NSTG   3
#define ROWB   144                      // bytes per smem row (36 floats)
#define ASTG   (128 * ROWB)             // 18432 B per matrix per stage
#define STGB   (2 * ASTG)               // 36864 B per stage
#define SMEM_DYN (NSTG * STGB)          // 110592 B
#define EPS    133                      // epilogue smem row stride (floats)

__global__ void __launch_bounds__(256, 2)
gemm_tc(const float* __restrict__ A0, const float* __restrict__ A1,
        const float* __restrict__ A2,
        const float* __restrict__ W0, const float* __restrict__ W1,
        const float* __restrict__ W2,
        const float* __restrict__ b0, const float* __restrict__ b1,
        const float* __restrict__ b2,
        float* __restrict__ C_ext, int mode_base)
{
    extern __shared__ char smem_raw[];
    __shared__ float bias_s[128];
    const uint32_t sb = smem_u32(smem_raw);

    const int z = blockIdx.z;
    const int mode = mode_base + z;
    const float* A    = (mode == 3) ? g_C : (z == 0 ? A0 : z == 1 ? A1 : A2);
    const float* W    = (z == 0) ? W0 : (z == 1) ? W1 : W2;
    const float* bias = (z == 0) ? b0 : (z == 1) ? b1 : b2;

    const int tid  = threadIdx.x;
    const int wid  = tid >> 5, lane = tid & 31;
    const int wm   = wid >> 2, wn = wid & 3;          // warp grid 2 x 4
    const int m0   = blockIdx.y * 128, n0 = blockIdx.x * 128;

    if (tid < 128) bias_s[tid] = bias[n0 + tid];

    float acc[4][4][4] = {};                          // [mi][ni][reg]

    auto load_chunk = [&](int c) {
        uint32_t base = sb + (uint32_t)(c % NSTG) * STGB;
        const float* Ag = A + (size_t)m0 * DM + c * KC;
        const float* Wg = W + (size_t)n0 * DM + c * KC;
        #pragma unroll
        for (int i = 0; i < 4; i++) {
            int q = tid + 256 * i;                    // 0..1023
            int r = q >> 3, c16 = q & 7;              // row, 16B segment
            uint32_t dst = base + (uint32_t)(r * ROWB + c16 * 16);
            cp_async16(dst,        (const char*)(Ag + (size_t)r * DM) + c16 * 16);
            cp_async16(dst + ASTG, (const char*)(Wg + (size_t)r * DM) + c16 * 16);
        }
    };

    load_chunk(0); cp_commit();
    load_chunk(1); cp_commit();

    const int a_row  = lane & 15;
    const int a_half = (lane >> 4) & 1;
    const uint32_t a_off0 = (uint32_t)((wm * 64 + a_row) * ROWB + a_half * 16);
    const int bg     = lane >> 3;
    const int b_nrow = (bg >> 1) * 8 + (lane & 7);
    const int b_half = bg & 1;
    const uint32_t b_off0 = (uint32_t)(ASTG + (wn * 32 + b_nrow) * ROWB + b_half * 16);

    const int NCH = DM / KC;                          // 32
    for (int c = 0; c < NCH; c++) {
        cp_wait<1>();
        __syncthreads();
        uint32_t base = sb + (uint32_t)(c % NSTG) * STGB;

        #pragma unroll
        for (int kk = 0; kk < 4; kk++) {
            uint32_t a[4][4], b[4][2];
            #pragma unroll
            for (int mi = 0; mi < 4; mi++)
                ldsm_x4(a[mi][0], a[mi][1], a[mi][2], a[mi][3],
                        base + a_off0 + (uint32_t)(mi * 16 * ROWB + kk * 32));
            #pragma unroll
            for (int np = 0; np < 2; np++) {
                uint32_t r0, r1, r2, r3;
                ldsm_x4(r0, r1, r2, r3,
                        base + b_off0 + (uint32_t)(np * 16 * ROWB + kk * 32));
                b[np * 2][0] = r0;     b[np * 2][1] = r1;
                b[np * 2 + 1][0] = r2; b[np * 2 + 1][1] = r3;
            }
            #pragma unroll
            for (int mi = 0; mi < 4; mi++)
                #pragma unroll
                for (int j = 0; j < 4; j++) a[mi][j] = f2tf32(a[mi][j]);
            #pragma unroll
            for (int ni = 0; ni < 4; ni++) {
                b[ni][0] = f2tf32(b[ni][0]);
                b[ni][1] = f2tf32(b[ni][1]);
            }
            #pragma unroll
            for (int mi = 0; mi < 4; mi++)
                #pragma unroll
                for (int ni = 0; ni < 4; ni++)
                    mma_tf32(acc[mi][ni], a[mi], b[ni]);
        }

        int cn = c + 2;
        if (cn < NCH) load_chunk(cn);
        cp_commit();                                  // one group per iteration
    }

    // ---------------- epilogue: regs -> smem -> coalesced gmem -------------
    __syncthreads();
    float* smemT = (float*)smem_raw;                  // 128 x EPS floats
    {
        const int r0 = wm * 64 + (lane >> 2);
        const int cc0 = wn * 32 + 2 * (lane & 3);
        #pragma unroll
        for (int mi = 0; mi < 4; mi++) {
            #pragma unroll
            for (int ni = 0; ni < 4; ni++) {
                int r = r0 + mi * 16, cc = cc0 + ni * 8;
                smemT[r * EPS + cc]           = acc[mi][ni][0];
                smemT[r * EPS + cc + 1]       = acc[mi][ni][1];
                smemT[(r + 8) * EPS + cc]     = acc[mi][ni][2];
                smemT[(r + 8) * EPS + cc + 1] = acc[mi][ni][3];
            }
        }
    }
    __syncthreads();

    const int bq = m0 >> 9, s_base = m0 & 511;
    if (mode == 2) {
        // transposed store: g_Vt[b][h][d][t], tf32-rounded (feeds mma only)
        #pragma unroll
        for (int i = 0; i < 16; i++) {
            int q = tid + 256 * i;                    // 0..4095
            int cc = q >> 5;                          // n-col 0..127
            int sc4 = (q & 31) * 4;                   // s-chunk
            float4 v;
            v.x = f2tf32f(smemT[(sc4 + 0) * EPS + cc] + bias_s[cc]);
            v.y = f2tf32f(smemT[(sc4 + 1) * EPS + cc] + bias_s[cc]);
            v.z = f2tf32f(smemT[(sc4 + 2) * EPS + cc] + bias_s[cc]);
            v.w = f2tf32f(smemT[(sc4 + 3) * EPS + cc] + bias_s[cc]);
            int n = n0 + cc;
            int h = n >> 6, d = n & 63;
            *(float4*)(g_Vt + ((size_t)(bq * NH + h) * DKH + d) * SEQ + s_base + sc4) = v;
        }
    } else if (mode < 2) {
        float* Cq = (mode == 0) ? g_Q : g_K;          // tf32-rounded (feeds mma only)
        #pragma unroll
        for (int i = 0; i < 16; i++) {
            int q = tid + 256 * i;
            int r = q >> 5, c4 = (q & 31) * 4;
            float4 v;
            v.x = f2tf32f(smemT[r * EPS + c4 + 0] + bias_s[c4 + 0]);
            v.y = f2tf32f(smemT[r * EPS + c4 + 1] + bias_s[c4 + 1]);
            v.z = f2tf32f(smemT[r * EPS + c4 + 2] + bias_s[c4 + 2]);
            v.w = f2tf32f(smemT[r * EPS + c4 + 3] + bias_s[c4 + 3]);
            int n = n0 + c4;
            int h = n >> 6, db = n & 63;
            *(float4*)(Cq + ((size_t)(bq * NH + h) * SEQ + s_base + r) * DKH + db) = v;
        }
    } else {
        // final output: FULL precision
        #pragma unroll
        for (int i = 0; i < 16; i++) {
            int q = tid + 256 * i;
            int r = q >> 5, c4 = (q & 31) * 4;
            float4 v;
            v.x = smemT[r * EPS + c4 + 0] + bias_s[c4 + 0];
            v.y = smemT[r * EPS + c4 + 1] + bias_s[c4 + 1];
            v.z = smemT[r * EPS + c4 + 2] + bias_s[c4 + 2];
            v.w = smemT[r * EPS + c4 + 3] + bias_s[c4 + 3];
            *(float4*)(C_ext + (size_t)(m0 + r) * DM + n0 + c4) = v;
        }
    }
}

// ---------------------------------------------------------------------------
// FULLY FUSED attention: scores + bias + causal softmax + P-write + ctx.
//   Q/K/Vt are pre-rounded to tf32 -> NO cvt in mma phases.
//   P strip rounded once during softmax normalize (smem); gmem P full precision.
// ---------------------------------------------------------------------------
#define TS       32                           // s rows per block
#define SCS      516                          // strip row stride (floats)
#define F_Q_OFF  (TS * SCS * 4)               // 66048
#define F_K_OFF  (F_Q_OFF + TS * 272)         // 74752
#define F_SMEM   (F_K_OFF + 2 * 64 * 272)     // 109568

__global__ void __launch_bounds__(256, 2)
attn_fused(const float* __restrict__ rel_bias)
{
    extern __shared__ char sm[];
    float* sc = (float*)sm;
    const uint32_t sb = smem_u32(sm);
    const uint32_t qb = sb + F_Q_OFF;

    const int bh = blockIdx.x;
    const int st = 15 - blockIdx.y;           // heavy tiles first
    const int h  = bh & 15, b = bh >> 4;
    const int s0 = st * TS;
    const int nt = (st >> 1) + 1;             // 64-wide t tiles
    const int tcap64 = nt * 64;

    const float* Qp = g_Q  + (size_t)bh * SEQ * DKH;
    const float* Kp = g_K  + (size_t)bh * SEQ * DKH;
    const float* Vp = g_Vt + (size_t)bh * DKH * SEQ;
    const float* rb = rel_bias + (size_t)h * SEQ * SEQ;
    float* Pp = g_P + (size_t)bh * SEQ * SEQ;

    const int tid = threadIdx.x, wid = tid >> 5, lane = tid & 31;
    const int wm = wid >> 2, wn = wid & 3;    // 2 x 4 warps; warp tile 16x16

    // group 0: Q tile (32x64) + K tile 0 (64x64)
    #pragma unroll
    for (int i = 0; i < 2; i++) {
        int q = tid + 256 * i;
        int r = q >> 4, seg = q & 15;
        cp_async16(qb + (uint32_t)(r * 272 + seg * 16),
                   Qp + (size_t)(s0 + r) * DKH + seg * 4);
    }
    #pragma unroll
    for (int i = 0; i < 4; i++) {
        int q = tid + 256 * i;
        int r = q >> 4, seg = q & 15;
        cp_async16(sb + F_K_OFF + (uint32_t)(r * 272 + seg * 16),
                   Kp + (size_t)r * DKH + seg * 4);
    }
    cp_commit();

    const int a_row = lane & 15, a_half = lane >> 4;
    const int bg = lane >> 3, b_nrow = (bg >> 1) * 8 + (lane & 7), b_half = bg & 1;
    uint32_t aq[8][4];

    // ---------------- phase 1: scores -> smem strip -------------------------
    for (int tt = 0; tt < nt; tt++) {
        int t0 = tt * 64;
        if (tt + 1 < nt) {
            uint32_t kb = sb + F_K_OFF + (uint32_t)(((tt + 1) & 1) * (64 * 272));
            #pragma unroll
            for (int i = 0; i < 4; i++) {
                int q = tid + 256 * i;
                int r = q >> 4, seg = q & 15;
                cp_async16(kb + (uint32_t)(r * 272 + seg * 16),
                           Kp + (size_t)(t0 + 64 + r) * DKH + seg * 4);
            }
            cp_commit();
            cp_wait<1>();
        } else {
            cp_wait<0>();
        }
        __syncthreads();

        if (tt == 0) {   // preload Q fragments once (already tf32)
            #pragma unroll
            for (int kk = 0; kk < 8; kk++)
                ldsm_x4(aq[kk][0], aq[kk][1], aq[kk][2], aq[kk][3],
                        qb + (uint32_t)((wm * 16 + a_row) * 272 + a_half * 16 + kk * 32));
        }

        uint32_t kb = sb + F_K_OFF + (uint32_t)((tt & 1) * (64 * 272));
        float acc[2][4] = {};
        #pragma unroll
        for (int kk = 0; kk < 8; kk++) {
            uint32_t bb[2][2];
            {
                uint32_t r0, r1, r2, r3;
                ldsm_x4(r0, r1, r2, r3,
                        kb + (uint32_t)((wn * 16 + b_nrow) * 272 + b_half * 16 + kk * 32));
                bb[0][0] = r0; bb[0][1] = r1;
                bb[1][0] = r2; bb[1][1] = r3;
            }
            mma_tf32(acc[0], aq[kk], bb[0]);
            mma_tf32(acc[1], aq[kk], bb[1]);
        }

        {
            int r = wm * 16 + (lane >> 2);
            #pragma unroll
            for (int ni = 0; ni < 2; ni++) {
                int t = t0 + wn * 16 + ni * 8 + (lane & 3) * 2;
                float2 rb0 = *(const float2*)&rb[(size_t)(s0 + r) * SEQ + t];
                float2 rb1 = *(const float2*)&rb[(size_t)(s0 + r + 8) * SEQ + t];
                *(float2*)&sc[r * SCS + t] =
                    make_float2(acc[ni][0] * 0.125f + rb0.x, acc[ni][1] * 0.125f + rb0.y);
                *(float2*)&sc[(r + 8) * SCS + t] =
                    make_float2(acc[ni][2] * 0.125f + rb1.x, acc[ni][3] * 0.125f + rb1.y);
            }
        }
        __syncthreads();
    }

    // kick V tile 0 load (overlaps with softmax); K buffers are free now
    {
        uint32_t vb = sb + F_K_OFF;
        #pragma unroll
        for (int i = 0; i < 4; i++) {
            int q = tid + 256 * i;
            int r = q >> 4, seg = q & 15;
            cp_async16(vb + (uint32_t)(r * 272 + seg * 16),
                       Vp + (size_t)r * SEQ + seg * 4);
        }
        cp_commit();
    }

    // -------- phase 2: causal softmax; gmem P full-prec, smem strip tf32 ----
    const int tcap4 = tcap64 >> 2;
    #pragma unroll
    for (int rr = 0; rr < 4; rr++) {
        int row = wid * 4 + rr;
        int s = s0 + row;
        float* srow = sc + row * SCS;
        int n = s + 1;

        float mx = -INFINITY;
        for (int t = lane; t < n; t += 32) mx = fmaxf(mx, srow[t]);
        #pragma unroll
        for (int o = 16; o; o >>= 1) mx = fmaxf(mx, __shfl_xor_sync(0xffffffffu, mx, o));

        float sum = 0.f;
        for (int t = lane; t < n; t += 32) {
            float e = __expf(srow[t] - mx);
            srow[t] = e;
            sum += e;
        }
        #pragma unroll
        for (int o = 16; o; o >>= 1) sum += __shfl_xor_sync(0xffffffffu, sum, o);

        for (int t = n + lane; t < tcap64; t += 32) srow[t] = 0.f;
        float inv = 1.0f / sum;
        __syncwarp();

        for (int q4 = lane; q4 < tcap4; q4 += 32) {
            float4 v = *(float4*)&srow[q4 * 4];
            v.x *= inv; v.y *= inv; v.z *= inv; v.w *= inv;
            *(float4*)&Pp[(size_t)s * SEQ + q4 * 4] = v;       // full precision to gmem
            v.x = f2tf32f(v.x); v.y = f2tf32f(v.y);
            v.z = f2tf32f(v.z); v.w = f2tf32f(v.w);
            *(float4*)&srow[q4 * 4] = v;                       // rounded for mma
        }
        __syncwarp();
    }
    __syncthreads();

    // ---------------- phase 3: ctx = P @ V^T from the strip -----------------
    float accc[2][4] = {};
    for (int c = 0; c < nt; c++) {
        if (c + 1 < nt) {
            uint32_t vb = sb + F_K_OFF + (uint32_t)(((c + 1) & 1) * (64 * 272));
            #pragma unroll
            for (int i = 0; i < 4; i++) {
                int q = tid + 256 * i;
                int r = q >> 4, seg = q & 15;
                cp_async16(vb + (uint32_t)(r * 272 + seg * 16),
                           Vp + (size_t)r * SEQ + (c + 1) * 64 + seg * 4);
            }
            cp_commit();
            cp_wait<1>();
        } else {
            cp_wait<0>();
        }
        __syncthreads();

        uint32_t vb = sb + F_K_OFF + (uint32_t)((c & 1) * (64 * 272));
        #pragma unroll
        for (int kk = 0; kk < 8; kk++) {
            uint32_t a[4], bb[2][2];
            ldsm_x4(a[0], a[1], a[2], a[3],
                    sb + (uint32_t)((wm * 16 + a_row) * (SCS * 4) + c * 256
                                    + a_half * 16 + kk * 32));
            {
                uint32_t r0, r1, r2, r3;
                ldsm_x4(r0, r1, r2, r3,
                        vb + (uint32_t)((wn * 16 + b_nrow) * 272 + b_half * 16 + kk * 32));
                bb[0][0] = r0; bb[0][1] = r1;
                bb[1][0] = r2; bb[1][1] = r3;
            }
            mma_tf32(accc[0], a, bb[0]);
            mma_tf32(accc[1], a, bb[1]);
        }
        __syncthreads();
    }

    {
        int r = wm * 16 + (lane >> 2);
        #pragma unroll
        for (int ni = 0; ni < 2; ni++) {
            int cc = wn * 16 + ni * 8 + (lane & 3) * 2;
            size_t o = ((size_t)(b * SEQ) + s0 + r) * DM + h * DKH + cc;
            *(float2*)&g_C[o]          = make_float2(accc[ni][0], accc[ni][1]);
            *(float2*)&g_C[o + 8 * DM] = make_float2(accc[ni][2], accc[ni][3]);
        }
    }
}

// ---------------------------------------------------------------------------
// attn_mean[b,s,t4..t4+3] = (1/16) * sum_h P[b,h,s,t] ; 0 for t > s (causal)
// ---------------------------------------------------------------------------
__global__ void __launch_bounds__(256) attn_mean_kernel(float* __restrict__ outp)
{
    size_t idx = (size_t)blockIdx.x * 256 + threadIdx.x;   // < B*S*S/4
    int t4 = (int)(idx & 127) * 4;
    int s  = (int)((idx >> 7) & 511);
    int b  = (int)(idx >> 16);
    float4 acc = make_float4(0.f, 0.f, 0.f, 0.f);
    if (t4 <= s) {
        const float* base = g_P + ((size_t)(b * NH) * SEQ + s) * SEQ + t4;
        #pragma unroll
        for (int h = 0; h < NH; h++) {
            float4 v = *(const float4*)(base + (size_t)h * SEQ * SEQ);
            acc.x += v.x; acc.y += v.y; acc.z += v.z; acc.w += v.w;
        }
        acc.x *= (1.0f / 16.0f);
        acc.y = (t4 + 1 <= s) ? acc.y * (1.0f / 16.0f) : 0.f;
        acc.z = (t4 + 2 <= s) ? acc.z * (1.0f / 16.0f) : 0.f;
        acc.w = (t4 + 3 <= s) ? acc.w * (1.0f / 16.0f) : 0.f;
    }
    *(float4*)&outp[idx * 4] = acc;
}

// ---------------------------------------------------------------------------
// Launch
// ---------------------------------------------------------------------------
extern "C" void kernel_launch(void* const* d_in, const int* in_sizes, int n_in,
                              void* d_out, int out_size)
{
    const float* query    = (const float*)d_in[0];
    const float* key      = (const float*)d_in[1];
    const float* value    = (const float*)d_in[2];
    const float* wq_w     = (const float*)d_in[3];
    const float* wq_b     = (const float*)d_in[4];
    const float* wk_w     = (const float*)d_in[5];
    const float* wk_b     = (const float*)d_in[6];
    const float* wv_w     = (const float*)d_in[7];
    const float* wv_b     = (const float*)d_in[8];
    const float* wo_w     = (const float*)d_in[9];
    const float* wo_b     = (const float*)d_in[10];
    const float* rel_bias = (const float*)d_in[11];

    float* out       = (float*)d_out;
    float* attn_mean = out + (size_t)BQ * SEQ * DM;

    static int smem_set = 0;
    if (!smem_set) {
        cudaFuncSetAttribute(gemm_tc,    cudaFuncAttributeMaxDynamicSharedMemorySize, SMEM_DYN);
        cudaFuncSetAttribute(attn_fused, cudaFuncAttributeMaxDynamicSharedMemorySize, F_SMEM);
        smem_set = 1;
    }

    // fused QKV projections: one launch, grid.z selects {Q,K,V}
    dim3 gQKV(DM / 128, MROWS / 128, 3);
    gemm_tc<<<gQKV, 256, SMEM_DYN>>>(query, key, value,
                                     wq_w, wk_w, wv_w,
                                     wq_b, wk_b, wv_b,
                                     nullptr, 0);

    attn_fused<<<dim3(BQ * NH, 16), 256, F_SMEM>>>(rel_bias);
    attn_mean_kernel<<<(BQ * SEQ * SEQ / 4) / 256, 256>>>(attn_mean);

    // output projection (mode 3)
    dim3 gO(DM / 128, MROWS / 128, 1);
    gemm_tc<<<gO, 256, SMEM_DYN>>>(nullptr, nullptr, nullptr,
                                   wo_w, nullptr, nullptr,
                                   wo_b, nullptr, nullptr,
                                   out, 3);
}

// round 17
// speedup vs baseline: 3.6579x; 1.0589x over previous
#include <cuda_runtime.h>
#include <math.h>
#include <stdint.h>

// Problem constants
#define BQ   16
#define SEQ  512
#define NH   16
#define DKH  64
#define DM   1024
#define MROWS (BQ * SEQ)   // 8192

// ---------------------------------------------------------------------------
// Scratch (device globals; allocation-free per harness rules)
// ---------------------------------------------------------------------------
__device__ float g_Q[BQ * NH * SEQ * DKH];            // [b][h][s][d]   (tf32-rounded)
__device__ float g_K[BQ * NH * SEQ * DKH];            // [b][h][t][d]   (tf32-rounded)
__device__ float g_Vt[BQ * NH * DKH * SEQ];           // [b][h][d][t]   (tf32-rounded)
__device__ float g_P[(size_t)BQ * NH * SEQ * SEQ];    // [b][h][s][t]   probs (lower tri)
__device__ float g_C[BQ * SEQ * DM];                  // [b][s][h*64+d] (tf32-rounded)

// tf32-rounded copies of GEMM inputs (pre-pass)
__device__ float g_Aq[MROWS * DM];
__device__ float g_Ak[MROWS * DM];
__device__ float g_Av[MROWS * DM];
__device__ float g_Wq[DM * DM];
__device__ float g_Wk[DM * DM];
__device__ float g_Wv[DM * DM];
__device__ float g_Wo[DM * DM];

// ---------------------------------------------------------------------------
// PTX helpers (base-target legal: sm_80+ features only)
// ---------------------------------------------------------------------------
__device__ __forceinline__ uint32_t smem_u32(const void* p) {
    return (uint32_t)__cvta_generic_to_shared((void*)p);
}
__device__ __forceinline__ void cp_async16(uint32_t dst, const void* src) {
    asm volatile("cp.async.cg.shared.global [%0], [%1], 16;" :: "r"(dst), "l"(src));
}
__device__ __forceinline__ void cp_commit() {
    asm volatile("cp.async.commit_group;" ::: "memory");
}
template <int N> __device__ __forceinline__ void cp_wait() {
    asm volatile("cp.async.wait_group %0;" :: "n"(N) : "memory");
}
__device__ __forceinline__ void ldsm_x4(uint32_t& r0, uint32_t& r1, uint32_t& r2,
                                        uint32_t& r3, uint32_t addr) {
    asm volatile("ldmatrix.sync.aligned.m8n8.x4.shared.b16 {%0,%1,%2,%3}, [%4];"
                 : "=r"(r0), "=r"(r1), "=r"(r2), "=r"(r3) : "r"(addr));
}
__device__ __forceinline__ float f2tf32f(float x) {
    uint32_t y;
    asm("cvt.rna.tf32.f32 %0, %1;" : "=r"(y) : "f"(x));
    return __uint_as_float(y);
}
__device__ __forceinline__ void mma_tf32(float* c, const uint32_t* a, const uint32_t* b) {
    asm volatile(
        "mma.sync.aligned.m16n8k8.row.col.f32.tf32.tf32.f32 "
        "{%0,%1,%2,%3}, {%4,%5,%6,%7}, {%8,%9}, {%0,%1,%2,%3};"
        : "+f"(c[0]), "+f"(c[1]), "+f"(c[2]), "+f"(c[3])
        : "r"(a[0]), "r"(a[1]), "r"(a[2]), "r"(a[3]), "r"(b[0]), "r"(b[1]));
}

// ---------------------------------------------------------------------------
// tf32 rounding pre-pass: dst[i] = round_tf32(src[i]) (float4 grid-stride)
// ---------------------------------------------------------------------------
__global__ void __launch_bounds__(256) round_tf32_kernel(const float4* __restrict__ src,
                                                         float4* __restrict__ dst, int n4)
{
    int i = blockIdx.x * 256 + threadIdx.x;
    int stride = gridDim.x * 256;
    for (; i < n4; i += stride) {
        float4 v = src[i];
        v.x = f2tf32f(v.x); v.y = f2tf32f(v.y);
        v.z = f2tf32f(v.z); v.w = f2tf32f(v.w);
        dst[i] = v;
    }
}

// ---------------------------------------------------------------------------
// tf32 mma.sync GEMM: C = A @ W^T + bias; M=8192, N=1024, K=1024
// Inputs PRE-ROUNDED to tf32 -> zero cvt in the mainloop.
// Tile 128x128, K-chunk 32, 3-stage cp.async pipeline, 2 CTAs/SM.
// mode = mode_base + blockIdx.z:
//   0/1: head-layout to g_Q/g_K (tf32-rounded)
//   2  : TRANSPOSED to g_Vt (tf32-rounded)
//   3  : g_C -> C_ext (full precision)
// ---------------------------------------------------------------------------
#define KC     32
#define NSTG   3
#define ROWB   144                      // bytes per smem row (36 floats)
#define ASTG   (128 * ROWB)             // 18432 B per matrix per stage
#define STGB   (2 * ASTG)               // 36864 B per stage
#define SMEM_DYN (NSTG * STGB)          // 110592 B
#define EPS    133                      // epilogue smem row stride (floats)

__global__ void __launch_bounds__(256, 2)
gemm_tc(const float* __restrict__ A0, const float* __restrict__ A1,
        const float* __restrict__ A2,
        const float* __restrict__ W0, const float* __restrict__ W1,
        const float* __restrict__ W2,
        const float* __restrict__ b0, const float* __restrict__ b1,
        const float* __restrict__ b2,
        float* __restrict__ C_ext, int mode_base)
{
    extern __shared__ char smem_raw[];
    __shared__ float bias_s[128];
    const uint32_t sb = smem_u32(smem_raw);

    const int z = blockIdx.z;
    const int mode = mode_base + z;
    const float* A    = (mode == 3) ? g_C : (z == 0 ? A0 : z == 1 ? A1 : A2);
    const float* W    = (z == 0) ? W0 : (z == 1) ? W1 : W2;
    const float* bias = (z == 0) ? b0 : (z == 1) ? b1 : b2;

    const int tid  = threadIdx.x;
    const int wid  = tid >> 5, lane = tid & 31;
    const int wm   = wid >> 2, wn = wid & 3;          // warp grid 2 x 4
    const int m0   = blockIdx.y * 128, n0 = blockIdx.x * 128;

    if (tid < 128) bias_s[tid] = bias[n0 + tid];

    float acc[4][4][4] = {};                          // [mi][ni][reg]

    auto load_chunk = [&](int c) {
        uint32_t base = sb + (uint32_t)(c % NSTG) * STGB;
        const float* Ag = A + (size_t)m0 * DM + c * KC;
        const float* Wg = W + (size_t)n0 * DM + c * KC;
        #pragma unroll
        for (int i = 0; i < 4; i++) {
            int q = tid + 256 * i;                    // 0..1023
            int r = q >> 3, c16 = q & 7;              // row, 16B segment
            uint32_t dst = base + (uint32_t)(r * ROWB + c16 * 16);
            cp_async16(dst,        (const char*)(Ag + (size_t)r * DM) + c16 * 16);
            cp_async16(dst + ASTG, (const char*)(Wg + (size_t)r * DM) + c16 * 16);
        }
    };

    load_chunk(0); cp_commit();
    load_chunk(1); cp_commit();

    const int a_row  = lane & 15;
    const int a_half = (lane >> 4) & 1;
    const uint32_t a_off0 = (uint32_t)((wm * 64 + a_row) * ROWB + a_half * 16);
    const int bg     = lane >> 3;
    const int b_nrow = (bg >> 1) * 8 + (lane & 7);
    const int b_half = bg & 1;
    const uint32_t b_off0 = (uint32_t)(ASTG + (wn * 32 + b_nrow) * ROWB + b_half * 16);

    const int NCH = DM / KC;                          // 32
    for (int c = 0; c < NCH; c++) {
        cp_wait<1>();
        __syncthreads();
        uint32_t base = sb + (uint32_t)(c % NSTG) * STGB;

        #pragma unroll
        for (int kk = 0; kk < 4; kk++) {
            uint32_t a[4][4], b[4][2];
            #pragma unroll
            for (int mi = 0; mi < 4; mi++)
                ldsm_x4(a[mi][0], a[mi][1], a[mi][2], a[mi][3],
                        base + a_off0 + (uint32_t)(mi * 16 * ROWB + kk * 32));
            #pragma unroll
            for (int np = 0; np < 2; np++) {
                uint32_t r0, r1, r2, r3;
                ldsm_x4(r0, r1, r2, r3,
                        base + b_off0 + (uint32_t)(np * 16 * ROWB + kk * 32));
                b[np * 2][0] = r0;     b[np * 2][1] = r1;
                b[np * 2 + 1][0] = r2; b[np * 2 + 1][1] = r3;
            }
            // inputs pre-rounded: no cvt here
            #pragma unroll
            for (int mi = 0; mi < 4; mi++)
                #pragma unroll
                for (int ni = 0; ni < 4; ni++)
                    mma_tf32(acc[mi][ni], a[mi], b[ni]);
        }

        int cn = c + 2;
        if (cn < NCH) load_chunk(cn);
        cp_commit();                                  // one group per iteration
    }

    // ---------------- epilogue: regs -> smem -> coalesced gmem -------------
    __syncthreads();
    float* smemT = (float*)smem_raw;                  // 128 x EPS floats
    {
        const int r0 = wm * 64 + (lane >> 2);
        const int cc0 = wn * 32 + 2 * (lane & 3);
        #pragma unroll
        for (int mi = 0; mi < 4; mi++) {
            #pragma unroll
            for (int ni = 0; ni < 4; ni++) {
                int r = r0 + mi * 16, cc = cc0 + ni * 8;
                smemT[r * EPS + cc]           = acc[mi][ni][0];
                smemT[r * EPS + cc + 1]       = acc[mi][ni][1];
                smemT[(r + 8) * EPS + cc]     = acc[mi][ni][2];
                smemT[(r + 8) * EPS + cc + 1] = acc[mi][ni][3];
            }
        }
    }
    __syncthreads();

    const int bq = m0 >> 9, s_base = m0 & 511;
    if (mode == 2) {
        // transposed store: g_Vt[b][h][d][t], tf32-rounded (feeds mma only)
        #pragma unroll
        for (int i = 0; i < 16; i++) {
            int q = tid + 256 * i;                    // 0..4095
            int cc = q >> 5;                          // n-col 0..127
            int sc4 = (q & 31) * 4;                   // s-chunk
            float4 v;
            v.x = f2tf32f(smemT[(sc4 + 0) * EPS + cc] + bias_s[cc]);
            v.y = f2tf32f(smemT[(sc4 + 1) * EPS + cc] + bias_s[cc]);
            v.z = f2tf32f(smemT[(sc4 + 2) * EPS + cc] + bias_s[cc]);
            v.w = f2tf32f(smemT[(sc4 + 3) * EPS + cc] + bias_s[cc]);
            int n = n0 + cc;
            int h = n >> 6, d = n & 63;
            *(float4*)(g_Vt + ((size_t)(bq * NH + h) * DKH + d) * SEQ + s_base + sc4) = v;
        }
    } else if (mode < 2) {
        float* Cq = (mode == 0) ? g_Q : g_K;          // tf32-rounded (feeds mma only)
        #pragma unroll
        for (int i = 0; i < 16; i++) {
            int q = tid + 256 * i;
            int r = q >> 5, c4 = (q & 31) * 4;
            float4 v;
            v.x = f2tf32f(smemT[r * EPS + c4 + 0] + bias_s[c4 + 0]);
            v.y = f2tf32f(smemT[r * EPS + c4 + 1] + bias_s[c4 + 1]);
            v.z = f2tf32f(smemT[r * EPS + c4 + 2] + bias_s[c4 + 2]);
            v.w = f2tf32f(smemT[r * EPS + c4 + 3] + bias_s[c4 + 3]);
            int n = n0 + c4;
            int h = n >> 6, db = n & 63;
            *(float4*)(Cq + ((size_t)(bq * NH + h) * SEQ + s_base + r) * DKH + db) = v;
        }
    } else {
        // final output: FULL precision
        #pragma unroll
        for (int i = 0; i < 16; i++) {
            int q = tid + 256 * i;
            int r = q >> 5, c4 = (q & 31) * 4;
            float4 v;
            v.x = smemT[r * EPS + c4 + 0] + bias_s[c4 + 0];
            v.y = smemT[r * EPS + c4 + 1] + bias_s[c4 + 1];
            v.z = smemT[r * EPS + c4 + 2] + bias_s[c4 + 2];
            v.w = smemT[r * EPS + c4 + 3] + bias_s[c4 + 3];
            *(float4*)(C_ext + (size_t)(m0 + r) * DM + n0 + c4) = v;
        }
    }
}

// ---------------------------------------------------------------------------
// FULLY FUSED attention: scores + bias + causal softmax + P-write + ctx.
//   Q/K/Vt pre-rounded -> no cvt in mma phases. g_C stored tf32-rounded
//   (feeds only the pre-rounded output-proj mma).
// ---------------------------------------------------------------------------
#define TS       32                           // s rows per block
#define SCS      516                          // strip row stride (floats)
#define F_Q_OFF  (TS * SCS * 4)               // 66048
#define F_K_OFF  (F_Q_OFF + TS * 272)         // 74752
#define F_SMEM   (F_K_OFF + 2 * 64 * 272)     // 109568

__global__ void __launch_bounds__(256, 2)
attn_fused(const float* __restrict__ rel_bias)
{
    extern __shared__ char sm[];
    float* sc = (float*)sm;
    const uint32_t sb = smem_u32(sm);
    const uint32_t qb = sb + F_Q_OFF;

    const int bh = blockIdx.x;
    const int st = 15 - blockIdx.y;           // heavy tiles first
    const int h  = bh & 15, b = bh >> 4;
    const int s0 = st * TS;
    const int nt = (st >> 1) + 1;             // 64-wide t tiles
    const int tcap64 = nt * 64;

    const float* Qp = g_Q  + (size_t)bh * SEQ * DKH;
    const float* Kp = g_K  + (size_t)bh * SEQ * DKH;
    const float* Vp = g_Vt + (size_t)bh * DKH * SEQ;
    const float* rb = rel_bias + (size_t)h * SEQ * SEQ;
    float* Pp = g_P + (size_t)bh * SEQ * SEQ;

    const int tid = threadIdx.x, wid = tid >> 5, lane = tid & 31;
    const int wm = wid >> 2, wn = wid & 3;    // 2 x 4 warps; warp tile 16x16

    // group 0: Q tile (32x64) + K tile 0 (64x64)
    #pragma unroll
    for (int i = 0; i < 2; i++) {
        int q = tid + 256 * i;
        int r = q >> 4, seg = q & 15;
        cp_async16(qb + (uint32_t)(r * 272 + seg * 16),
                   Qp + (size_t)(s0 + r) * DKH + seg * 4);
    }
    #pragma unroll
    for (int i = 0; i < 4; i++) {
        int q = tid + 256 * i;
        int r = q >> 4, seg = q & 15;
        cp_async16(sb + F_K_OFF + (uint32_t)(r * 272 + seg * 16),
                   Kp + (size_t)r * DKH + seg * 4);
    }
    cp_commit();

    const int a_row = lane & 15, a_half = lane >> 4;
    const int bg = lane >> 3, b_nrow = (bg >> 1) * 8 + (lane & 7), b_half = bg & 1;
    uint32_t aq[8][4];

    // ---------------- phase 1: scores -> smem strip -------------------------
    for (int tt = 0; tt < nt; tt++) {
        int t0 = tt * 64;
        if (tt + 1 < nt) {
            uint32_t kb = sb + F_K_OFF + (uint32_t)(((tt + 1) & 1) * (64 * 272));
            #pragma unroll
            for (int i = 0; i < 4; i++) {
                int q = tid + 256 * i;
                int r = q >> 4, seg = q & 15;
                cp_async16(kb + (uint32_t)(r * 272 + seg * 16),
                           Kp + (size_t)(t0 + 64 + r) * DKH + seg * 4);
            }
            cp_commit();
            cp_wait<1>();
        } else {
            cp_wait<0>();
        }
        __syncthreads();

        if (tt == 0) {   // preload Q fragments once (already tf32)
            #pragma unroll
            for (int kk = 0; kk < 8; kk++)
                ldsm_x4(aq[kk][0], aq[kk][1], aq[kk][2], aq[kk][3],
                        qb + (uint32_t)((wm * 16 + a_row) * 272 + a_half * 16 + kk * 32));
        }

        uint32_t kb = sb + F_K_OFF + (uint32_t)((tt & 1) * (64 * 272));
        float acc[2][4] = {};
        #pragma unroll
        for (int kk = 0; kk < 8; kk++) {
            uint32_t bb[2][2];
            {
                uint32_t r0, r1, r2, r3;
                ldsm_x4(r0, r1, r2, r3,
                        kb + (uint32_t)((wn * 16 + b_nrow) * 272 + b_half * 16 + kk * 32));
                bb[0][0] = r0; bb[0][1] = r1;
                bb[1][0] = r2; bb[1][1] = r3;
            }
            mma_tf32(acc[0], aq[kk], bb[0]);
            mma_tf32(acc[1], aq[kk], bb[1]);
        }

        {
            int r = wm * 16 + (lane >> 2);
            #pragma unroll
            for (int ni = 0; ni < 2; ni++) {
                int t = t0 + wn * 16 + ni * 8 + (lane & 3) * 2;
                float2 rb0 = *(const float2*)&rb[(size_t)(s0 + r) * SEQ + t];
                float2 rb1 = *(const float2*)&rb[(size_t)(s0 + r + 8) * SEQ + t];
                *(float2*)&sc[r * SCS + t] =
                    make_float2(acc[ni][0] * 0.125f + rb0.x, acc[ni][1] * 0.125f + rb0.y);
                *(float2*)&sc[(r + 8) * SCS + t] =
                    make_float2(acc[ni][2] * 0.125f + rb1.x, acc[ni][3] * 0.125f + rb1.y);
            }
        }
        __syncthreads();
    }

    // kick V tile 0 load (overlaps with softmax); K buffers are free now
    {
        uint32_t vb = sb + F_K_OFF;
        #pragma unroll
        for (int i = 0; i < 4; i++) {
            int q = tid + 256 * i;
            int r = q >> 4, seg = q & 15;
            cp_async16(vb + (uint32_t)(r * 272 + seg * 16),
                       Vp + (size_t)r * SEQ + seg * 4);
        }
        cp_commit();
    }

    // -------- phase 2: causal softmax; gmem P full-prec, smem strip tf32 ----
    const int tcap4 = tcap64 >> 2;
    #pragma unroll
    for (int rr = 0; rr < 4; rr++) {
        int row = wid * 4 + rr;
        int s = s0 + row;
        float* srow = sc + row * SCS;
        int n = s + 1;

        float mx = -INFINITY;
        for (int t = lane; t < n; t += 32) mx = fmaxf(mx, srow[t]);
        #pragma unroll
        for (int o = 16; o; o >>= 1) mx = fmaxf(mx, __shfl_xor_sync(0xffffffffu, mx, o));

        float sum = 0.f;
        for (int t = lane; t < n; t += 32) {
            float e = __expf(srow[t] - mx);
            srow[t] = e;
            sum += e;
        }
        #pragma unroll
        for (int o = 16; o; o >>= 1) sum += __shfl_xor_sync(0xffffffffu, sum, o);

        for (int t = n + lane; t < tcap64; t += 32) srow[t] = 0.f;
        float inv = 1.0f / sum;
        __syncwarp();

        for (int q4 = lane; q4 < tcap4; q4 += 32) {
            float4 v = *(float4*)&srow[q4 * 4];
            v.x *= inv; v.y *= inv; v.z *= inv; v.w *= inv;
            *(float4*)&Pp[(size_t)s * SEQ + q4 * 4] = v;       // full precision to gmem
            v.x = f2tf32f(v.x); v.y = f2tf32f(v.y);
            v.z = f2tf32f(v.z); v.w = f2tf32f(v.w);
            *(float4*)&srow[q4 * 4] = v;                       // rounded for mma
        }
        __syncwarp();
    }
    __syncthreads();

    // ---------------- phase 3: ctx = P @ V^T from the strip -----------------
    float accc[2][4] = {};
    for (int c = 0; c < nt; c++) {
        if (c + 1 < nt) {
            uint32_t vb = sb + F_K_OFF + (uint32_t)(((c + 1) & 1) * (64 * 272));
            #pragma unroll
            for (int i = 0; i < 4; i++) {
                int q = tid + 256 * i;
                int r = q >> 4, seg = q & 15;
                cp_async16(vb + (uint32_t)(r * 272 + seg * 16),
                           Vp + (size_t)r * SEQ + (c + 1) * 64 + seg * 4);
            }
            cp_commit();
            cp_wait<1>();
        } else {
            cp_wait<0>();
        }
        __syncthreads();

        uint32_t vb = sb + F_K_OFF + (uint32_t)((c & 1) * (64 * 272));
        #pragma unroll
        for (int kk = 0; kk < 8; kk++) {
            uint32_t a[4], bb[2][2];
            ldsm_x4(a[0], a[1], a[2], a[3],
                    sb + (uint32_t)((wm * 16 + a_row) * (SCS * 4) + c * 256
                                    + a_half * 16 + kk * 32));
            {
                uint32_t r0, r1, r2, r3;
                ldsm_x4(r0, r1, r2, r3,
                        vb + (uint32_t)((wn * 16 + b_nrow) * 272 + b_half * 16 + kk * 32));
                bb[0][0] = r0; bb[0][1] = r1;
                bb[1][0] = r2; bb[1][1] = r3;
            }
            mma_tf32(accc[0], a, bb[0]);
            mma_tf32(accc[1], a, bb[1]);
        }
        __syncthreads();
    }

    {
        int r = wm * 16 + (lane >> 2);
        #pragma unroll
        for (int ni = 0; ni < 2; ni++) {
            int cc = wn * 16 + ni * 8 + (lane & 3) * 2;
            size_t o = ((size_t)(b * SEQ) + s0 + r) * DM + h * DKH + cc;
            // tf32-rounded: g_C feeds only the (pre-rounded) output-proj mma
            *(float2*)&g_C[o] =
                make_float2(f2tf32f(accc[ni][0]), f2tf32f(accc[ni][1]));
            *(float2*)&g_C[o + 8 * DM] =
                make_float2(f2tf32f(accc[ni][2]), f2tf32f(accc[ni][3]));
        }
    }
}

// ---------------------------------------------------------------------------
// attn_mean[b,s,t4..t4+3] = (1/16) * sum_h P[b,h,s,t] ; 0 for t > s (causal)
// ---------------------------------------------------------------------------
__global__ void __launch_bounds__(256) attn_mean_kernel(float* __restrict__ outp)
{
    size_t idx = (size_t)blockIdx.x * 256 + threadIdx.x;   // < B*S*S/4
    int t4 = (int)(idx & 127) * 4;
    int s  = (int)((idx >> 7) & 511);
    int b  = (int)(idx >> 16);
    float4 acc = make_float4(0.f, 0.f, 0.f, 0.f);
    if (t4 <= s) {
        const float* base = g_P + ((size_t)(b * NH) * SEQ + s) * SEQ + t4;
        #pragma unroll
        for (int h = 0; h < NH; h++) {
            float4 v = *(const float4*)(base + (size_t)h * SEQ * SEQ);
            acc.x += v.x; acc.y += v.y; acc.z += v.z; acc.w += v.w;
        }
        acc.x *= (1.0f / 16.0f);
        acc.y = (t4 + 1 <= s) ? acc.y * (1.0f / 16.0f) : 0.f;
        acc.z = (t4 + 2 <= s) ? acc.z * (1.0f / 16.0f) : 0.f;
        acc.w = (t4 + 3 <= s) ? acc.w * (1.0f / 16.0f) : 0.f;
    }
    *(float4*)&outp[idx * 4] = acc;
}

// ---------------------------------------------------------------------------
// Launch
// ---------------------------------------------------------------------------
extern "C" void kernel_launch(void* const* d_in, const int* in_sizes, int n_in,
                              void* d_out, int out_size)
{
    const float* query    = (const float*)d_in[0];
    const float* key      = (const float*)d_in[1];
    const float* value    = (const float*)d_in[2];
    const float* wq_w     = (const float*)d_in[3];
    const float* wq_b     = (const float*)d_in[4];
    const float* wk_w     = (const float*)d_in[5];
    const float* wk_b     = (const float*)d_in[6];
    const float* wv_w     = (const float*)d_in[7];
    const float* wv_b     = (const float*)d_in[8];
    const float* wo_w     = (const float*)d_in[9];
    const float* wo_b     = (const float*)d_in[10];
    const float* rel_bias = (const float*)d_in[11];

    float* out       = (float*)d_out;
    float* attn_mean = out + (size_t)BQ * SEQ * DM;

    static int smem_set = 0;
    if (!smem_set) {
        cudaFuncSetAttribute(gemm_tc,    cudaFuncAttributeMaxDynamicSharedMemorySize, SMEM_DYN);
        cudaFuncSetAttribute(attn_fused, cudaFuncAttributeMaxDynamicSharedMemorySize, F_SMEM);
        smem_set = 1;
    }

    // device-global rounded buffers (addresses via cudaGetSymbolAddress-free path:
    // use a tiny helper kernel-independent trick — symbols are directly usable
    // in device code; host just needs the launches below in order)
    // tf32 pre-round pass (in = 8M floats each, W = 1M floats each)
    {
        const int IN4 = MROWS * DM / 4;      // 2097152
        const int W4  = DM * DM / 4;         // 262144
        float4 *dAq, *dAk, *dAv, *dWq, *dWk, *dWv, *dWo;
        cudaGetSymbolAddress((void**)&dAq, g_Aq);
        cudaGetSymbolAddress((void**)&dAk, g_Ak);
        cudaGetSymbolAddress((void**)&dAv, g_Av);
        cudaGetSymbolAddress((void**)&dWq, g_Wq);
        cudaGetSymbolAddress((void**)&dWk, g_Wk);
        cudaGetSymbolAddress((void**)&dWv, g_Wv);
        cudaGetSymbolAddress((void**)&dWo, g_Wo);
        round_tf32_kernel<<<4096, 256>>>((const float4*)query, dAq, IN4);
        round_tf32_kernel<<<4096, 256>>>((const float4*)key,   dAk, IN4);
        round_tf32_kernel<<<4096, 256>>>((const float4*)value, dAv, IN4);
        round_tf32_kernel<<<1024, 256>>>((const float4*)wq_w,  dWq, W4);
        round_tf32_kernel<<<1024, 256>>>((const float4*)wk_w,  dWk, W4);
        round_tf32_kernel<<<1024, 256>>>((const float4*)wv_w,  dWv, W4);
        round_tf32_kernel<<<1024, 256>>>((const float4*)wo_w,  dWo, W4);

        // fused QKV projections: one launch, grid.z selects {Q,K,V}
        dim3 gQKV(DM / 128, MROWS / 128, 3);
        gemm_tc<<<gQKV, 256, SMEM_DYN>>>((const float*)dAq, (const float*)dAk,
                                         (const float*)dAv,
                                         (const float*)dWq, (const float*)dWk,
                                         (const float*)dWv,
                                         wq_b, wk_b, wv_b,
                                         nullptr, 0);

        attn_fused<<<dim3(BQ * NH, 16), 256, F_SMEM>>>(rel_bias);
        attn_mean_kernel<<<(BQ * SEQ * SEQ / 4) / 256, 256>>>(attn_mean);

        // output projection (mode 3)
        dim3 gO(DM / 128, MROWS / 128, 1);
        gemm_tc<<<gO, 256, SMEM_DYN>>>(nullptr, nullptr, nullptr,
                                       (const float*)dWo, nullptr, nullptr,
                                       wo_b, nullptr, nullptr,
                                       out, 3);
    }
}